// round 11
// baseline (speedup 1.0000x reference)
#include <cuda_runtime.h>
#include <cuda_fp16.h>
#include <cstdint>

#define BHN 128
#define LN  512
#define DN  128
#define LQN 64
#define INV_SQRT_D 0.08838834764831843f

#define SSTR 136
#define OFF_QHI  0
#define OFF_QLO  8704
#define OFF_B0   17408
#define OFF_B1   52224
#define OFF_PHI  87040      // also used as the rel staging tile (8 KB) pre-PV
#define OFF_PLO  95744
#define OFF_MASK 104448
#define OFF_RMAX 106496
#define OFF_RSUM 107008
#define SMEM_T   107520

__device__ __half g_Kh[(size_t)BHN * LN * DN];           // 16 MB
__device__ __half g_Vh[(size_t)BHN * LN * DN];           // 16 MB

__device__ __forceinline__ uint32_t smem_u32(const void* p) {
    uint32_t a;
    asm("{ .reg .u64 t; cvta.to.shared.u64 t, %1; cvt.u32.u64 %0, t; }" : "=r"(a) : "l"(p));
    return a;
}
__device__ __forceinline__ uint32_t pack_h2(float a, float b) {
    __half2 h = __floats2half2_rn(a, b);    // .x = a (low half)
    return *(uint32_t*)&h;
}

#define LDSM_X4(r0, r1, r2, r3, addr)                                           \
    asm volatile("ldmatrix.sync.aligned.m8n8.x4.shared.b16 {%0,%1,%2,%3}, [%4];"\
                 : "=r"(r0), "=r"(r1), "=r"(r2), "=r"(r3) : "r"(addr))
#define LDSM_X4_T(r0, r1, r2, r3, addr)                                         \
    asm volatile("ldmatrix.sync.aligned.m8n8.x4.trans.shared.b16 {%0,%1,%2,%3}, [%4];"\
                 : "=r"(r0), "=r"(r1), "=r"(r2), "=r"(r3) : "r"(addr))
#define MMA_F16(c, a, b)                                                        \
    asm volatile("mma.sync.aligned.m16n8k16.row.col.f32.f16.f16.f32 "           \
                 "{%0,%1,%2,%3}, {%4,%5,%6,%7}, {%8,%9}, {%0,%1,%2,%3};"        \
                 : "+f"((c)[0]), "+f"((c)[1]), "+f"((c)[2]), "+f"((c)[3])       \
                 : "r"((a)[0]), "r"((a)[1]), "r"((a)[2]), "r"((a)[3]),          \
                   "r"((b)[0]), "r"((b)[1]))

#define CP16(dst, src)  asm volatile("cp.async.cg.shared.global [%0], [%1], 16;" :: "r"(dst), "l"(src))
#define CP_COMMIT()     asm volatile("cp.async.commit_group;" ::: "memory")
#define CP_WAIT1()      asm volatile("cp.async.wait_group 1;" ::: "memory")
#define CP_WAIT0()      asm volatile("cp.async.wait_group 0;" ::: "memory")

// convert float4 (row r, cols 4*c4..) into hi/lo fp16 smem tiles (stride SSTR)
__device__ __forceinline__ void cvt_store(char* smem, int hi, int lo,
                                          int r, int c4, float4 v) {
    uint32_t off = (uint32_t)(r * SSTR + c4 * 4) * 2u;
    float hx = __half2float(__float2half_rn(v.x));
    float hy = __half2float(__float2half_rn(v.y));
    float hz = __half2float(__float2half_rn(v.z));
    float hw = __half2float(__float2half_rn(v.w));
    *(uint2*)(smem + hi + off) = make_uint2(pack_h2(v.x, v.y), pack_h2(v.z, v.w));
    *(uint2*)(smem + lo + off) = make_uint2(pack_h2(v.x - hx, v.y - hy),
                                            pack_h2(v.z - hz, v.w - hw));
}

// async-load one 128x128 fp16 chunk into buffer at bufoff (128 threads)
__device__ __forceinline__ void load_chunk(uint32_t sb, uint32_t bufoff,
                                           const __half* src, size_t base, int tid) {
    #pragma unroll
    for (int i = 0; i < 16; i++) {
        int idx = tid + 128 * i;         // 0..2047
        int r = idx >> 4, c8 = idx & 15;
        uint32_t doff = (uint32_t)(r * (SSTR * 2) + c8 * 16);
        CP16(sb + bufoff + doff, src + base + (size_t)r * DN + c8 * 8);
    }
}

// QK chunk MMA: A = Q hi/lo (K-major), B = chunk at bufoff (K-major), m32 x n32
__device__ __forceinline__ void mma_qk(uint32_t sb, uint32_t bufoff, int warp_n,
                                       int lane, float acc[2][4][4]) {
    const int ar = lane & 15, acs = (lane >> 4) << 3;
    const int br = (lane & 7) | ((lane >> 4) << 3), bcs = ((lane >> 3) & 1) << 3;
    const uint32_t ab[2] = {sb + OFF_QHI, sb + OFF_QLO};
    #pragma unroll
    for (int ch = 0; ch < 2; ch++) {
        #pragma unroll
        for (int k16 = 0; k16 < 8; k16++) {
            const int kh = k16 * 16;
            uint32_t a[2][4];
            #pragma unroll
            for (int mt = 0; mt < 2; mt++)
                LDSM_X4(a[mt][0], a[mt][1], a[mt][2], a[mt][3],
                        ab[ch] + (uint32_t)((mt * 16 + ar) * SSTR + kh + acs) * 2u);
            uint32_t bf[4][2];
            #pragma unroll
            for (int p = 0; p < 2; p++) {
                uint32_t r0, r1, r2, r3;
                LDSM_X4(r0, r1, r2, r3,
                        sb + bufoff + (uint32_t)((warp_n + p * 16 + br) * SSTR + kh + bcs) * 2u);
                bf[2*p][0] = r0; bf[2*p][1] = r1;
                bf[2*p+1][0] = r2; bf[2*p+1][1] = r3;
            }
            #pragma unroll
            for (int mt = 0; mt < 2; mt++)
                #pragma unroll
                for (int nt = 0; nt < 4; nt++) MMA_F16(acc[mt][nt], a[mt], bf[nt]);
        }
    }
}

// PV chunk MMA: A = P hi/lo (K-major), B = chunk at bufoff [k][d] via trans
__device__ __forceinline__ void mma_pv(uint32_t sb, uint32_t bufoff, int warp_n,
                                       int lane, float acc[2][4][4]) {
    const int ar = lane & 15, acs = (lane >> 4) << 3;
    const int tkr = lane & 15, tnc = (lane >> 4) << 3;
    const uint32_t ab[2] = {sb + OFF_PHI, sb + OFF_PLO};
    #pragma unroll
    for (int ch = 0; ch < 2; ch++) {
        #pragma unroll
        for (int k16 = 0; k16 < 8; k16++) {
            const int kh = k16 * 16;
            uint32_t a[2][4];
            #pragma unroll
            for (int mt = 0; mt < 2; mt++)
                LDSM_X4(a[mt][0], a[mt][1], a[mt][2], a[mt][3],
                        ab[ch] + (uint32_t)((mt * 16 + ar) * SSTR + kh + acs) * 2u);
            uint32_t bf[4][2];
            #pragma unroll
            for (int p = 0; p < 2; p++) {
                uint32_t r0, r1, r2, r3;
                LDSM_X4_T(r0, r1, r2, r3,
                          sb + bufoff + (uint32_t)((kh + tkr) * SSTR + warp_n + p * 16 + tnc) * 2u);
                bf[2*p][0] = r0; bf[2*p][1] = r1;
                bf[2*p+1][0] = r2; bf[2*p+1][1] = r3;
            }
            #pragma unroll
            for (int mt = 0; mt < 2; mt++)
                #pragma unroll
                for (int nt = 0; nt < 4; nt++) MMA_F16(acc[mt][nt], a[mt], bf[nt]);
        }
    }
}

// ---------------------------------------------------------------------------
// prep: K,V fp32 -> fp16 global scratch (single rounding)
// ---------------------------------------------------------------------------
__global__ __launch_bounds__(256) void prep_kernel(const float* __restrict__ K,
                                                   const float* __restrict__ V)
{
    size_t i4 = (size_t)blockIdx.x * 256 + threadIdx.x;
    const float* src = blockIdx.y ? V : K;
    __half* dst = blockIdx.y ? g_Vh : g_Kh;
    float4 v = ((const float4*)src)[i4];
    ((uint2*)dst)[i4] = make_uint2(pack_h2(v.x, v.y), pack_h2(v.z, v.w));
}

// ---------------------------------------------------------------------------
// fused: QK + inline-rel + softmax + attn write + PV; 128 thr, 4 warps, 2 CTA/SM
// ---------------------------------------------------------------------------
__global__ __launch_bounds__(128, 2) void fused_attn(const float* __restrict__ Q,
                                                     const float* __restrict__ R,
                                                     const float* __restrict__ Mask,
                                                     float* __restrict__ attn,
                                                     float* __restrict__ out)
{
    extern __shared__ char smem[];
    const int tid = threadIdx.x, wid = tid >> 5, lane = tid & 31;
    const uint32_t sb = smem_u32(smem);
    const int b = blockIdx.y, qt = blockIdx.x;
    const size_t bkv = (size_t)b * LN * DN;
    const uint32_t buf[2] = {OFF_B0, OFF_B1};

    // prologue: K0 -> buf0, K1 -> buf1
    load_chunk(sb, OFF_B0, g_Kh, bkv, tid);
    CP_COMMIT();
    load_chunk(sb, OFF_B1, g_Kh, bkv + 128 * DN, tid);
    CP_COMMIT();

    {
        float* sm = (float*)(smem + OFF_MASK);
        #pragma unroll
        for (int i = 0; i < 4; i++) {
            int idx = tid + 128 * i;
            float m = Mask[(size_t)b * LN + idx];
            sm[idx] = (m != 0.f) ? logf(1.f - m) : 0.f;
        }
    }
    {
        const float* Qg = Q + ((size_t)b * LN + qt * 32) * DN;
        #pragma unroll
        for (int i = 0; i < 8; i++) {
            int idx = tid + 128 * i;
            int r = idx >> 5, c4 = idx & 31;
            cvt_store(smem, OFF_QHI, OFF_QLO, r, c4, *(const float4*)(Qg + r * DN + c4 * 4));
        }
    }

    // ---- inline rel (only blocks covering q rows >= 448): stage into OFF_PHI ----
    // relS[qp][kp] = dot(R[b, qp0+qp, kp, :], Q[b, qt*32+qp, :]) in fp32.
    // Each warp owns local rows wid*8 .. wid*8+7; results read after QK-loop syncs.
    if (qt >= 14) {
        const int qp0 = (qt - 14) * 32;
        const float* Qg = Q + ((size_t)b * LN + qt * 32) * DN;
        const float* Rg = R + ((size_t)b * LQN + qp0) * LQN * DN;
        float* relS = (float*)(smem + OFF_PHI);
        #pragma unroll
        for (int rr = 0; rr < 8; rr++) {
            const int qp = wid * 8 + rr;
            const float4 qv = ((const float4*)(Qg + (size_t)qp * DN))[lane];
            const float4* Rrow = (const float4*)(Rg + (size_t)qp * LQN * DN);
            #pragma unroll 4
            for (int kp = 0; kp < 64; kp++) {
                float4 rv = __ldcs(&Rrow[kp * 32 + lane]);   // single-use stream
                float s = rv.x * qv.x + rv.y * qv.y + rv.z * qv.z + rv.w * qv.w;
                s += __shfl_xor_sync(0xffffffffu, s, 16);
                s += __shfl_xor_sync(0xffffffffu, s, 8);
                s += __shfl_xor_sync(0xffffffffu, s, 4);
                s += __shfl_xor_sync(0xffffffffu, s, 2);
                s += __shfl_xor_sync(0xffffffffu, s, 1);
                if (lane == 0) relS[qp * 64 + kp] = s;
            }
        }
    }

    const int warp_n = wid * 32;
    const int rq = lane >> 2, cq = (lane & 3) * 2;

    float accS[4][2][4][4];
    #pragma unroll
    for (int kb = 0; kb < 4; kb++)
        #pragma unroll
        for (int mt = 0; mt < 2; mt++)
            #pragma unroll
            for (int nt = 0; nt < 4; nt++)
                #pragma unroll
                for (int j = 0; j < 4; j++) accS[kb][mt][nt][j] = 0.f;

    // ---- QK: stage s computes chunk s from buf[s&1], prefetches s+2 (K2,K3,V0,V1) ----
    #pragma unroll
    for (int s = 0; s < 4; s++) {
        CP_WAIT1();
        __syncthreads();
        mma_qk(sb, buf[s & 1], warp_n, lane, accS[s]);
        __syncthreads();
        if (s < 2) load_chunk(sb, buf[s & 1], g_Kh, bkv + (size_t)(s + 2) * 128 * DN, tid);
        else       load_chunk(sb, buf[s & 1], g_Vh, bkv + (size_t)(s - 2) * 128 * DN, tid);
        CP_COMMIT();
    }

    // ---- rel add from smem staging: rows 448.. (qt>=14), cols 448.. (chunk 3, warps 2,3) ----
    if (qt >= 14 && wid >= 2) {
        const float* relS = (const float*)(smem + OFF_PHI);
        #pragma unroll
        for (int mt = 0; mt < 2; mt++) {
            const int row0 = mt * 16 + rq;       // local q row
            #pragma unroll
            for (int nt = 0; nt < 4; nt++) {
                int kp = (wid - 2) * 32 + nt * 8 + cq;
                float2 s0 = *(const float2*)&relS[row0 * 64 + kp];
                float2 s1 = *(const float2*)&relS[(row0 + 8) * 64 + kp];
                accS[3][mt][nt][0] += s0.x; accS[3][mt][nt][1] += s0.y;
                accS[3][mt][nt][2] += s1.x; accS[3][mt][nt][3] += s1.y;
            }
        }
    }

    // ---- scale + mask + row max ----
    const float* sm = (const float*)(smem + OFF_MASK);
    float mx[2][2];
    mx[0][0] = mx[0][1] = mx[1][0] = mx[1][1] = -1e30f;
    #pragma unroll
    for (int kb = 0; kb < 4; kb++)
        #pragma unroll
        for (int mt = 0; mt < 2; mt++)
            #pragma unroll
            for (int nt = 0; nt < 4; nt++) {
                int c = kb * 128 + warp_n + nt * 8 + cq;
                float ml0 = sm[c], ml1 = sm[c + 1];
                float* a = accS[kb][mt][nt];
                a[0] = fmaf(a[0], INV_SQRT_D, ml0);
                a[1] = fmaf(a[1], INV_SQRT_D, ml1);
                a[2] = fmaf(a[2], INV_SQRT_D, ml0);
                a[3] = fmaf(a[3], INV_SQRT_D, ml1);
                mx[mt][0] = fmaxf(mx[mt][0], fmaxf(a[0], a[1]));
                mx[mt][1] = fmaxf(mx[mt][1], fmaxf(a[2], a[3]));
            }
    #pragma unroll
    for (int mt = 0; mt < 2; mt++)
        #pragma unroll
        for (int h = 0; h < 2; h++) {
            mx[mt][h] = fmaxf(mx[mt][h], __shfl_xor_sync(0xffffffffu, mx[mt][h], 1));
            mx[mt][h] = fmaxf(mx[mt][h], __shfl_xor_sync(0xffffffffu, mx[mt][h], 2));
        }
    float* rmax = (float*)(smem + OFF_RMAX);
    if ((lane & 3) == 0)
        #pragma unroll
        for (int mt = 0; mt < 2; mt++)
            #pragma unroll
            for (int h = 0; h < 2; h++)
                rmax[(mt * 16 + h * 8 + rq) * 4 + wid] = mx[mt][h];
    __syncthreads();
    #pragma unroll
    for (int mt = 0; mt < 2; mt++)
        #pragma unroll
        for (int h = 0; h < 2; h++) {
            const float* r4 = &rmax[(mt * 16 + h * 8 + rq) * 4];
            mx[mt][h] = fmaxf(fmaxf(r4[0], r4[1]), fmaxf(r4[2], r4[3]));
        }

    // ---- exp + row sum ----
    float sum[2][2] = {{0.f, 0.f}, {0.f, 0.f}};
    #pragma unroll
    for (int kb = 0; kb < 4; kb++)
        #pragma unroll
        for (int mt = 0; mt < 2; mt++)
            #pragma unroll
            for (int nt = 0; nt < 4; nt++) {
                float* a = accS[kb][mt][nt];
                a[0] = __expf(a[0] - mx[mt][0]); a[1] = __expf(a[1] - mx[mt][0]);
                a[2] = __expf(a[2] - mx[mt][1]); a[3] = __expf(a[3] - mx[mt][1]);
                sum[mt][0] += a[0] + a[1]; sum[mt][1] += a[2] + a[3];
            }
    #pragma unroll
    for (int mt = 0; mt < 2; mt++)
        #pragma unroll
        for (int h = 0; h < 2; h++) {
            sum[mt][h] += __shfl_xor_sync(0xffffffffu, sum[mt][h], 1);
            sum[mt][h] += __shfl_xor_sync(0xffffffffu, sum[mt][h], 2);
        }
    float* rsum = (float*)(smem + OFF_RSUM);
    if ((lane & 3) == 0)
        #pragma unroll
        for (int mt = 0; mt < 2; mt++)
            #pragma unroll
            for (int h = 0; h < 2; h++)
                rsum[(mt * 16 + h * 8 + rq) * 4 + wid] = sum[mt][h];
    __syncthreads();
    float inv[2][2];
    #pragma unroll
    for (int mt = 0; mt < 2; mt++)
        #pragma unroll
        for (int h = 0; h < 2; h++) {
            const float* r4 = &rsum[(mt * 16 + h * 8 + rq) * 4];
            inv[mt][h] = 1.f / (r4[0] + r4[1] + r4[2] + r4[3]);
        }

    // ---- normalize + write attn (streaming stores: single-use data) ----
    float* attnB = attn + ((size_t)b * LN + qt * 32) * LN;
    #pragma unroll
    for (int kb = 0; kb < 4; kb++)
        #pragma unroll
        for (int mt = 0; mt < 2; mt++) {
            const int r0 = mt * 16 + rq, r1 = r0 + 8;
            #pragma unroll
            for (int nt = 0; nt < 4; nt++) {
                int c = kb * 128 + warp_n + nt * 8 + cq;
                float* a = accS[kb][mt][nt];
                a[0] *= inv[mt][0]; a[1] *= inv[mt][0];
                a[2] *= inv[mt][1]; a[3] *= inv[mt][1];
                __stcs((float2*)(attnB + (size_t)r0 * LN + c), make_float2(a[0], a[1]));
                __stcs((float2*)(attnB + (size_t)r1 * LN + c), make_float2(a[2], a[3]));
            }
        }

    // ---- PV: stage s computes chunk s from buf[s&1], prefetches V s+2 ----
    float accO[2][4][4];
    #pragma unroll
    for (int mt = 0; mt < 2; mt++)
        #pragma unroll
        for (int nt = 0; nt < 4; nt++)
            #pragma unroll
            for (int j = 0; j < 4; j++) accO[mt][nt][j] = 0.f;

    __syncthreads();   // relS no longer needed; OFF_PHI becomes the P tile
    #pragma unroll
    for (int s = 0; s < 4; s++) {
        // P chunk s -> fp16 hi/lo smem
        #pragma unroll
        for (int mt = 0; mt < 2; mt++) {
            const int r0 = mt * 16 + rq, r1 = r0 + 8;
            #pragma unroll
            for (int nt = 0; nt < 4; nt++) {
                int c = warp_n + nt * 8 + cq;
                const float* a = accS[s][mt][nt];
                float h0 = __half2float(__float2half_rn(a[0]));
                float h1 = __half2float(__float2half_rn(a[1]));
                float h2 = __half2float(__float2half_rn(a[2]));
                float h3 = __half2float(__float2half_rn(a[3]));
                uint32_t o0 = (uint32_t)(r0 * SSTR + c) * 2u;
                uint32_t o1 = (uint32_t)(r1 * SSTR + c) * 2u;
                *(uint32_t*)(smem + OFF_PHI + o0) = pack_h2(a[0], a[1]);
                *(uint32_t*)(smem + OFF_PLO + o0) = pack_h2(a[0] - h0, a[1] - h1);
                *(uint32_t*)(smem + OFF_PHI + o1) = pack_h2(a[2], a[3]);
                *(uint32_t*)(smem + OFF_PLO + o1) = pack_h2(a[2] - h2, a[3] - h3);
            }
        }
        if (s < 3) { CP_WAIT1(); } else { CP_WAIT0(); }
        __syncthreads();
        mma_pv(sb, buf[s & 1], warp_n, lane, accO);
        __syncthreads();
        if (s < 2) {
            load_chunk(sb, buf[s & 1], g_Vh, bkv + (size_t)(s + 2) * 128 * DN, tid);
            CP_COMMIT();
        }
    }

    // ---- write out ----
    float* Og = out + ((size_t)b * LN + qt * 32) * DN;
    #pragma unroll
    for (int mt = 0; mt < 2; mt++) {
        const int r0 = mt * 16 + rq, r1 = r0 + 8;
        #pragma unroll
        for (int nt = 0; nt < 4; nt++) {
            int c = warp_n + nt * 8 + cq;
            __stcs((float2*)(Og + (size_t)r0 * DN + c), make_float2(accO[mt][nt][0], accO[mt][nt][1]));
            __stcs((float2*)(Og + (size_t)r1 * DN + c), make_float2(accO[mt][nt][2], accO[mt][nt][3]));
        }
    }
}

// ---------------------------------------------------------------------------
extern "C" void kernel_launch(void* const* d_in, const int* in_sizes, int n_in,
                              void* d_out, int out_size)
{
    const float* Q  = (const float*)d_in[0];
    const float* K  = (const float*)d_in[1];
    const float* V  = (const float*)d_in[2];
    const float* R  = (const float*)d_in[3];
    const float* M  = (const float*)d_in[4];

    float* out  = (float*)d_out;                       // [128,512,128]
    float* attn = out + (size_t)BHN * LN * DN;         // [128,512,512]

    static bool attr_set = false;
    if (!attr_set) {
        cudaFuncSetAttribute(fused_attn, cudaFuncAttributeMaxDynamicSharedMemorySize, SMEM_T);
        attr_set = true;
    }

    dim3 gprep((BHN * LN * DN) / 4 / 256, 2);          // (8192, 2)
    prep_kernel<<<gprep, 256>>>(K, V);

    dim3 g(16, BHN);                                   // (q-tiles, batch-heads)
    fused_attn<<<g, 128, SMEM_T>>>(Q, R, M, attn, out);
}

// round 12
// speedup vs baseline: 1.3744x; 1.3744x over previous
#include <cuda_runtime.h>
#include <cuda_fp16.h>
#include <cstdint>

#define BHN 128
#define LN  512
#define DN  128
#define LQN 64
#define INV_SQRT_D 0.08838834764831843f

#define SSTR 136
#define OFF_QHI  0
#define OFF_QLO  8704
#define OFF_B0   17408
#define OFF_B1   52224
#define OFF_PHI  87040
#define OFF_PLO  95744
#define OFF_MASK 104448
#define OFF_RMAX 106496
#define OFF_RSUM 107008
#define SMEM_T   107520

__device__ float g_Srel[(size_t)BHN * LQN * LQN];        // 2 MB
__device__ __half g_Kh[(size_t)BHN * LN * DN];           // 16 MB
__device__ __half g_Vh[(size_t)BHN * LN * DN];           // 16 MB

__device__ __forceinline__ uint32_t smem_u32(const void* p) {
    uint32_t a;
    asm("{ .reg .u64 t; cvta.to.shared.u64 t, %1; cvt.u32.u64 %0, t; }" : "=r"(a) : "l"(p));
    return a;
}
__device__ __forceinline__ uint32_t pack_h2(float a, float b) {
    __half2 h = __floats2half2_rn(a, b);    // .x = a (low half)
    return *(uint32_t*)&h;
}

#define LDSM_X4(r0, r1, r2, r3, addr)                                           \
    asm volatile("ldmatrix.sync.aligned.m8n8.x4.shared.b16 {%0,%1,%2,%3}, [%4];"\
                 : "=r"(r0), "=r"(r1), "=r"(r2), "=r"(r3) : "r"(addr))
#define LDSM_X4_T(r0, r1, r2, r3, addr)                                         \
    asm volatile("ldmatrix.sync.aligned.m8n8.x4.trans.shared.b16 {%0,%1,%2,%3}, [%4];"\
                 : "=r"(r0), "=r"(r1), "=r"(r2), "=r"(r3) : "r"(addr))
#define MMA_F16(c, a, b)                                                        \
    asm volatile("mma.sync.aligned.m16n8k16.row.col.f32.f16.f16.f32 "           \
                 "{%0,%1,%2,%3}, {%4,%5,%6,%7}, {%8,%9}, {%0,%1,%2,%3};"        \
                 : "+f"((c)[0]), "+f"((c)[1]), "+f"((c)[2]), "+f"((c)[3])       \
                 : "r"((a)[0]), "r"((a)[1]), "r"((a)[2]), "r"((a)[3]),          \
                   "r"((b)[0]), "r"((b)[1]))

#define CP16(dst, src)  asm volatile("cp.async.cg.shared.global [%0], [%1], 16;" :: "r"(dst), "l"(src))
#define CP_COMMIT()     asm volatile("cp.async.commit_group;" ::: "memory")
#define CP_WAIT1()      asm volatile("cp.async.wait_group 1;" ::: "memory")
#define CP_WAIT0()      asm volatile("cp.async.wait_group 0;" ::: "memory")

// convert float4 (row r, cols 4*c4..) into hi/lo fp16 smem tiles (stride SSTR)
__device__ __forceinline__ void cvt_store(char* smem, int hi, int lo,
                                          int r, int c4, float4 v) {
    uint32_t off = (uint32_t)(r * SSTR + c4 * 4) * 2u;
    float hx = __half2float(__float2half_rn(v.x));
    float hy = __half2float(__float2half_rn(v.y));
    float hz = __half2float(__float2half_rn(v.z));
    float hw = __half2float(__float2half_rn(v.w));
    *(uint2*)(smem + hi + off) = make_uint2(pack_h2(v.x, v.y), pack_h2(v.z, v.w));
    *(uint2*)(smem + lo + off) = make_uint2(pack_h2(v.x - hx, v.y - hy),
                                            pack_h2(v.z - hz, v.w - hw));
}

// async-load one 128x128 fp16 chunk into buffer at bufoff (128 threads)
__device__ __forceinline__ void load_chunk(uint32_t sb, uint32_t bufoff,
                                           const __half* src, size_t base, int tid) {
    #pragma unroll
    for (int i = 0; i < 16; i++) {
        int idx = tid + 128 * i;         // 0..2047
        int r = idx >> 4, c8 = idx & 15;
        uint32_t doff = (uint32_t)(r * (SSTR * 2) + c8 * 16);
        CP16(sb + bufoff + doff, src + base + (size_t)r * DN + c8 * 8);
    }
}

// QK chunk MMA: A = Q hi/lo (K-major), B = chunk at bufoff (K-major), m32 x n32
__device__ __forceinline__ void mma_qk(uint32_t sb, uint32_t bufoff, int warp_n,
                                       int lane, float acc[2][4][4]) {
    const int ar = lane & 15, acs = (lane >> 4) << 3;
    const int br = (lane & 7) | ((lane >> 4) << 3), bcs = ((lane >> 3) & 1) << 3;
    const uint32_t ab[2] = {sb + OFF_QHI, sb + OFF_QLO};
    #pragma unroll
    for (int ch = 0; ch < 2; ch++) {
        #pragma unroll
        for (int k16 = 0; k16 < 8; k16++) {
            const int kh = k16 * 16;
            uint32_t a[2][4];
            #pragma unroll
            for (int mt = 0; mt < 2; mt++)
                LDSM_X4(a[mt][0], a[mt][1], a[mt][2], a[mt][3],
                        ab[ch] + (uint32_t)((mt * 16 + ar) * SSTR + kh + acs) * 2u);
            uint32_t bf[4][2];
            #pragma unroll
            for (int p = 0; p < 2; p++) {
                uint32_t r0, r1, r2, r3;
                LDSM_X4(r0, r1, r2, r3,
                        sb + bufoff + (uint32_t)((warp_n + p * 16 + br) * SSTR + kh + bcs) * 2u);
                bf[2*p][0] = r0; bf[2*p][1] = r1;
                bf[2*p+1][0] = r2; bf[2*p+1][1] = r3;
            }
            #pragma unroll
            for (int mt = 0; mt < 2; mt++)
                #pragma unroll
                for (int nt = 0; nt < 4; nt++) MMA_F16(acc[mt][nt], a[mt], bf[nt]);
        }
    }
}

// PV chunk MMA: A = P hi/lo (K-major), B = chunk at bufoff [k][d] via trans
__device__ __forceinline__ void mma_pv(uint32_t sb, uint32_t bufoff, int warp_n,
                                       int lane, float acc[2][4][4]) {
    const int ar = lane & 15, acs = (lane >> 4) << 3;
    const int tkr = lane & 15, tnc = (lane >> 4) << 3;
    const uint32_t ab[2] = {sb + OFF_PHI, sb + OFF_PLO};
    #pragma unroll
    for (int ch = 0; ch < 2; ch++) {
        #pragma unroll
        for (int k16 = 0; k16 < 8; k16++) {
            const int kh = k16 * 16;
            uint32_t a[2][4];
            #pragma unroll
            for (int mt = 0; mt < 2; mt++)
                LDSM_X4(a[mt][0], a[mt][1], a[mt][2], a[mt][3],
                        ab[ch] + (uint32_t)((mt * 16 + ar) * SSTR + kh + acs) * 2u);
            uint32_t bf[4][2];
            #pragma unroll
            for (int p = 0; p < 2; p++) {
                uint32_t r0, r1, r2, r3;
                LDSM_X4_T(r0, r1, r2, r3,
                          sb + bufoff + (uint32_t)((kh + tkr) * SSTR + warp_n + p * 16 + tnc) * 2u);
                bf[2*p][0] = r0; bf[2*p][1] = r1;
                bf[2*p+1][0] = r2; bf[2*p+1][1] = r3;
            }
            #pragma unroll
            for (int mt = 0; mt < 2; mt++)
                #pragma unroll
                for (int nt = 0; nt < 4; nt++) MMA_F16(acc[mt][nt], a[mt], bf[nt]);
        }
    }
}

// ---------------------------------------------------------------------------
// prep: K,V fp32 -> fp16 global scratch (single rounding)
// ---------------------------------------------------------------------------
__global__ __launch_bounds__(256) void prep_kernel(const float* __restrict__ K,
                                                   const float* __restrict__ V)
{
    size_t i4 = (size_t)blockIdx.x * 256 + threadIdx.x;
    const float* src = blockIdx.y ? V : K;
    __half* dst = blockIdx.y ? g_Vh : g_Kh;
    float4 v = ((const float4*)src)[i4];
    ((uint2*)dst)[i4] = make_uint2(pack_h2(v.x, v.y), pack_h2(v.z, v.w));
}

// ---------------------------------------------------------------------------
// rel: g_Srel[b,q',k'] = dot(R[b,q',k',:], Q[b,448+q',:])  (streaming loads)
// ---------------------------------------------------------------------------
__global__ __launch_bounds__(256) void rel_kernel(const float* __restrict__ Q,
                                                  const float* __restrict__ R)
{
    __shared__ float qrow[DN];
    const int b  = blockIdx.x >> 6;
    const int qp = blockIdx.x & 63;
    const int tid = threadIdx.x;

    if (tid < 32)
        ((float4*)qrow)[tid] =
            *(const float4*)(Q + ((size_t)b * LN + (LN - LQN) + qp) * DN + tid * 4);
    __syncthreads();

    const int w = tid >> 5, lane = tid & 31;
    const float4 qv = ((const float4*)qrow)[lane];

    #pragma unroll
    for (int i = 0; i < 8; i++) {
        int kp = w + i * 8;
        const float4* rp = (const float4*)(R + (((size_t)b * LQN + qp) * LQN + kp) * DN);
        float4 rv = __ldcs(&rp[lane]);            // single-use stream; keep L2 for K/V
        float s = rv.x * qv.x + rv.y * qv.y + rv.z * qv.z + rv.w * qv.w;
        #pragma unroll
        for (int o = 16; o; o >>= 1) s += __shfl_xor_sync(0xffffffffu, s, o);
        if (lane == 0)
            g_Srel[((size_t)b * LQN + qp) * LQN + kp] = s;
    }
}

// ---------------------------------------------------------------------------
// fused: 128 threads, 4 warps, q-tile 32, m32 x n32 warp tiles, double-buffered B
// ---------------------------------------------------------------------------
__global__ __launch_bounds__(128, 2) void fused_attn(const float* __restrict__ Q,
                                                     const float* __restrict__ Mask,
                                                     float* __restrict__ attn,
                                                     float* __restrict__ out,
                                                     int qt_off)
{
    extern __shared__ char smem[];
    const int tid = threadIdx.x, wid = tid >> 5, lane = tid & 31;
    const uint32_t sb = smem_u32(smem);
    const int b = blockIdx.y, qt = blockIdx.x + qt_off;
    const size_t bkv = (size_t)b * LN * DN;
    const uint32_t buf[2] = {OFF_B0, OFF_B1};

    // prologue: K0 -> buf0, K1 -> buf1
    load_chunk(sb, OFF_B0, g_Kh, bkv, tid);
    CP_COMMIT();
    load_chunk(sb, OFF_B1, g_Kh, bkv + 128 * DN, tid);
    CP_COMMIT();

    {
        float* sm = (float*)(smem + OFF_MASK);
        #pragma unroll
        for (int i = 0; i < 4; i++) {
            int idx = tid + 128 * i;
            float m = Mask[(size_t)b * LN + idx];
            sm[idx] = (m != 0.f) ? logf(1.f - m) : 0.f;
        }
    }
    {
        const float* Qg = Q + ((size_t)b * LN + qt * 32) * DN;
        #pragma unroll
        for (int i = 0; i < 8; i++) {
            int idx = tid + 128 * i;
            int r = idx >> 5, c4 = idx & 31;
            cvt_store(smem, OFF_QHI, OFF_QLO, r, c4, *(const float4*)(Qg + r * DN + c4 * 4));
        }
    }

    const int warp_n = wid * 32;
    const int rq = lane >> 2, cq = (lane & 3) * 2;

    float accS[4][2][4][4];
    #pragma unroll
    for (int kb = 0; kb < 4; kb++)
        #pragma unroll
        for (int mt = 0; mt < 2; mt++)
            #pragma unroll
            for (int nt = 0; nt < 4; nt++)
                #pragma unroll
                for (int j = 0; j < 4; j++) accS[kb][mt][nt][j] = 0.f;

    // ---- QK: stage s computes chunk s from buf[s&1], prefetches s+2 (K2,K3,V0,V1) ----
    #pragma unroll
    for (int s = 0; s < 4; s++) {
        CP_WAIT1();
        __syncthreads();
        mma_qk(sb, buf[s & 1], warp_n, lane, accS[s]);
        __syncthreads();
        if (s < 2) load_chunk(sb, buf[s & 1], g_Kh, bkv + (size_t)(s + 2) * 128 * DN, tid);
        else       load_chunk(sb, buf[s & 1], g_Vh, bkv + (size_t)(s - 2) * 128 * DN, tid);
        CP_COMMIT();
    }

    // ---- rel add: rows 448.. (qt>=14), cols 448.. (chunk 3, warps 2,3) ----
    if (qt >= 14 && wid >= 2) {
        const int qp0 = (qt - 14) * 32;
        #pragma unroll
        for (int mt = 0; mt < 2; mt++) {
            const int row0 = qp0 + mt * 16 + rq;
            #pragma unroll
            for (int nt = 0; nt < 4; nt++) {
                int kp = (wid - 2) * 32 + nt * 8 + cq;
                float2 s0 = *(const float2*)&g_Srel[((size_t)b * LQN + row0) * LQN + kp];
                float2 s1 = *(const float2*)&g_Srel[((size_t)b * LQN + row0 + 8) * LQN + kp];
                accS[3][mt][nt][0] += s0.x; accS[3][mt][nt][1] += s0.y;
                accS[3][mt][nt][2] += s1.x; accS[3][mt][nt][3] += s1.y;
            }
        }
    }

    // ---- scale + mask + row max ----
    const float* sm = (const float*)(smem + OFF_MASK);
    float mx[2][2];
    mx[0][0] = mx[0][1] = mx[1][0] = mx[1][1] = -1e30f;
    #pragma unroll
    for (int kb = 0; kb < 4; kb++)
        #pragma unroll
        for (int mt = 0; mt < 2; mt++)
            #pragma unroll
            for (int nt = 0; nt < 4; nt++) {
                int c = kb * 128 + warp_n + nt * 8 + cq;
                float ml0 = sm[c], ml1 = sm[c + 1];
                float* a = accS[kb][mt][nt];
                a[0] = fmaf(a[0], INV_SQRT_D, ml0);
                a[1] = fmaf(a[1], INV_SQRT_D, ml1);
                a[2] = fmaf(a[2], INV_SQRT_D, ml0);
                a[3] = fmaf(a[3], INV_SQRT_D, ml1);
                mx[mt][0] = fmaxf(mx[mt][0], fmaxf(a[0], a[1]));
                mx[mt][1] = fmaxf(mx[mt][1], fmaxf(a[2], a[3]));
            }
    #pragma unroll
    for (int mt = 0; mt < 2; mt++)
        #pragma unroll
        for (int h = 0; h < 2; h++) {
            mx[mt][h] = fmaxf(mx[mt][h], __shfl_xor_sync(0xffffffffu, mx[mt][h], 1));
            mx[mt][h] = fmaxf(mx[mt][h], __shfl_xor_sync(0xffffffffu, mx[mt][h], 2));
        }
    float* rmax = (float*)(smem + OFF_RMAX);
    if ((lane & 3) == 0)
        #pragma unroll
        for (int mt = 0; mt < 2; mt++)
            #pragma unroll
            for (int h = 0; h < 2; h++)
                rmax[(mt * 16 + h * 8 + rq) * 4 + wid] = mx[mt][h];
    __syncthreads();
    #pragma unroll
    for (int mt = 0; mt < 2; mt++)
        #pragma unroll
        for (int h = 0; h < 2; h++) {
            const float* r4 = &rmax[(mt * 16 + h * 8 + rq) * 4];
            mx[mt][h] = fmaxf(fmaxf(r4[0], r4[1]), fmaxf(r4[2], r4[3]));
        }

    // ---- exp + row sum ----
    float sum[2][2] = {{0.f, 0.f}, {0.f, 0.f}};
    #pragma unroll
    for (int kb = 0; kb < 4; kb++)
        #pragma unroll
        for (int mt = 0; mt < 2; mt++)
            #pragma unroll
            for (int nt = 0; nt < 4; nt++) {
                float* a = accS[kb][mt][nt];
                a[0] = __expf(a[0] - mx[mt][0]); a[1] = __expf(a[1] - mx[mt][0]);
                a[2] = __expf(a[2] - mx[mt][1]); a[3] = __expf(a[3] - mx[mt][1]);
                sum[mt][0] += a[0] + a[1]; sum[mt][1] += a[2] + a[3];
            }
    #pragma unroll
    for (int mt = 0; mt < 2; mt++)
        #pragma unroll
        for (int h = 0; h < 2; h++) {
            sum[mt][h] += __shfl_xor_sync(0xffffffffu, sum[mt][h], 1);
            sum[mt][h] += __shfl_xor_sync(0xffffffffu, sum[mt][h], 2);
        }
    float* rsum = (float*)(smem + OFF_RSUM);
    if ((lane & 3) == 0)
        #pragma unroll
        for (int mt = 0; mt < 2; mt++)
            #pragma unroll
            for (int h = 0; h < 2; h++)
                rsum[(mt * 16 + h * 8 + rq) * 4 + wid] = sum[mt][h];
    __syncthreads();
    float inv[2][2];
    #pragma unroll
    for (int mt = 0; mt < 2; mt++)
        #pragma unroll
        for (int h = 0; h < 2; h++) {
            const float* r4 = &rsum[(mt * 16 + h * 8 + rq) * 4];
            inv[mt][h] = 1.f / (r4[0] + r4[1] + r4[2] + r4[3]);
        }

    // ---- normalize + write attn (streaming stores: single-use data) ----
    float* attnB = attn + ((size_t)b * LN + qt * 32) * LN;
    #pragma unroll
    for (int kb = 0; kb < 4; kb++)
        #pragma unroll
        for (int mt = 0; mt < 2; mt++) {
            const int r0 = mt * 16 + rq, r1 = r0 + 8;
            #pragma unroll
            for (int nt = 0; nt < 4; nt++) {
                int c = kb * 128 + warp_n + nt * 8 + cq;
                float* a = accS[kb][mt][nt];
                a[0] *= inv[mt][0]; a[1] *= inv[mt][0];
                a[2] *= inv[mt][1]; a[3] *= inv[mt][1];
                __stcs((float2*)(attnB + (size_t)r0 * LN + c), make_float2(a[0], a[1]));
                __stcs((float2*)(attnB + (size_t)r1 * LN + c), make_float2(a[2], a[3]));
            }
        }

    // ---- PV: stage s computes chunk s from buf[s&1], prefetches V s+2 ----
    float accO[2][4][4];
    #pragma unroll
    for (int mt = 0; mt < 2; mt++)
        #pragma unroll
        for (int nt = 0; nt < 4; nt++)
            #pragma unroll
            for (int j = 0; j < 4; j++) accO[mt][nt][j] = 0.f;

    #pragma unroll
    for (int s = 0; s < 4; s++) {
        // P chunk s -> fp16 hi/lo smem
        #pragma unroll
        for (int mt = 0; mt < 2; mt++) {
            const int r0 = mt * 16 + rq, r1 = r0 + 8;
            #pragma unroll
            for (int nt = 0; nt < 4; nt++) {
                int c = warp_n + nt * 8 + cq;
                const float* a = accS[s][mt][nt];
                float h0 = __half2float(__float2half_rn(a[0]));
                float h1 = __half2float(__float2half_rn(a[1]));
                float h2 = __half2float(__float2half_rn(a[2]));
                float h3 = __half2float(__float2half_rn(a[3]));
                uint32_t o0 = (uint32_t)(r0 * SSTR + c) * 2u;
                uint32_t o1 = (uint32_t)(r1 * SSTR + c) * 2u;
                *(uint32_t*)(smem + OFF_PHI + o0) = pack_h2(a[0], a[1]);
                *(uint32_t*)(smem + OFF_PLO + o0) = pack_h2(a[0] - h0, a[1] - h1);
                *(uint32_t*)(smem + OFF_PHI + o1) = pack_h2(a[2], a[3]);
                *(uint32_t*)(smem + OFF_PLO + o1) = pack_h2(a[2] - h2, a[3] - h3);
            }
        }
        if (s < 3) { CP_WAIT1(); } else { CP_WAIT0(); }
        __syncthreads();
        mma_pv(sb, buf[s & 1], warp_n, lane, accO);
        __syncthreads();
        if (s < 2) {
            load_chunk(sb, buf[s & 1], g_Vh, bkv + (size_t)(s + 2) * 128 * DN, tid);
            CP_COMMIT();
        }
    }

    // ---- write out ----
    float* Og = out + ((size_t)b * LN + qt * 32) * DN;
    #pragma unroll
    for (int mt = 0; mt < 2; mt++) {
        const int r0 = mt * 16 + rq, r1 = r0 + 8;
        #pragma unroll
        for (int nt = 0; nt < 4; nt++) {
            int c = warp_n + nt * 8 + cq;
            __stcs((float2*)(Og + (size_t)r0 * DN + c), make_float2(accO[mt][nt][0], accO[mt][nt][1]));
            __stcs((float2*)(Og + (size_t)r1 * DN + c), make_float2(accO[mt][nt][2], accO[mt][nt][3]));
        }
    }
}

// ---------------------------------------------------------------------------
extern "C" void kernel_launch(void* const* d_in, const int* in_sizes, int n_in,
                              void* d_out, int out_size)
{
    const float* Q  = (const float*)d_in[0];
    const float* K  = (const float*)d_in[1];
    const float* V  = (const float*)d_in[2];
    const float* R  = (const float*)d_in[3];
    const float* M  = (const float*)d_in[4];

    float* out  = (float*)d_out;                       // [128,512,128]
    float* attn = out + (size_t)BHN * LN * DN;         // [128,512,512]

    static cudaStream_t s1;
    static cudaEvent_t evFork, evRel;
    static bool init_done = false;
    if (!init_done) {
        cudaFuncSetAttribute(fused_attn, cudaFuncAttributeMaxDynamicSharedMemorySize, SMEM_T);
        cudaStreamCreateWithFlags(&s1, cudaStreamNonBlocking);
        cudaEventCreateWithFlags(&evFork, cudaEventDisableTiming);
        cudaEventCreateWithFlags(&evRel, cudaEventDisableTiming);
        init_done = true;
    }

    // fork: rel runs on s1 concurrently with prep + fused(qt<14) on the main stream
    cudaEventRecord(evFork, 0);
    cudaStreamWaitEvent(s1, evFork, 0);
    rel_kernel<<<BHN * LQN, 256, 0, s1>>>(Q, R);       // 8192 blocks, DRAM-bound
    cudaEventRecord(evRel, s1);

    dim3 gprep((BHN * LN * DN) / 4 / 256, 2);          // (8192, 2)
    prep_kernel<<<gprep, 256>>>(K, V);

    dim3 g1(14, BHN);                                  // q-tiles 0..13 (no rel needed)
    fused_attn<<<g1, 128, SMEM_T>>>(Q, M, attn, out, 0);

    // join: qt 14,15 need g_Srel
    cudaStreamWaitEvent(0, evRel, 0);
    dim3 g2(2, BHN);
    fused_attn<<<g2, 128, SMEM_T>>>(Q, M, attn, out, 14);
}

// round 13
// speedup vs baseline: 1.4657x; 1.0664x over previous
#include <cuda_runtime.h>
#include <cuda_fp16.h>
#include <cstdint>

#define BHN 128
#define LN  512
#define DN  128
#define LQN 64
#define INV_SQRT_D 0.08838834764831843f

#define SSTR 136
#define OFF_QHI  0
#define OFF_QLO  8704
#define OFF_B0   17408
#define OFF_B1   52224
#define OFF_PHI  87040
#define OFF_PLO  95744
#define OFF_MASK 104448
#define OFF_RMAX 106496
#define OFF_RSUM 107008
#define SMEM_T   107520

__device__ float g_Srel[(size_t)BHN * LQN * LQN];        // 2 MB
__device__ __half g_Kh[(size_t)BHN * LN * DN];           // 16 MB
__device__ __half g_Vh[(size_t)BHN * LN * DN];           // 16 MB

__device__ __forceinline__ uint32_t smem_u32(const void* p) {
    uint32_t a;
    asm("{ .reg .u64 t; cvta.to.shared.u64 t, %1; cvt.u32.u64 %0, t; }" : "=r"(a) : "l"(p));
    return a;
}
__device__ __forceinline__ uint32_t pack_h2(float a, float b) {
    __half2 h = __floats2half2_rn(a, b);    // .x = a (low half)
    return *(uint32_t*)&h;
}

#define LDSM_X4(r0, r1, r2, r3, addr)                                           \
    asm volatile("ldmatrix.sync.aligned.m8n8.x4.shared.b16 {%0,%1,%2,%3}, [%4];"\
                 : "=r"(r0), "=r"(r1), "=r"(r2), "=r"(r3) : "r"(addr))
#define LDSM_X4_T(r0, r1, r2, r3, addr)                                         \
    asm volatile("ldmatrix.sync.aligned.m8n8.x4.trans.shared.b16 {%0,%1,%2,%3}, [%4];"\
                 : "=r"(r0), "=r"(r1), "=r"(r2), "=r"(r3) : "r"(addr))
#define MMA_F16(c, a, b)                                                        \
    asm volatile("mma.sync.aligned.m16n8k16.row.col.f32.f16.f16.f32 "           \
                 "{%0,%1,%2,%3}, {%4,%5,%6,%7}, {%8,%9}, {%0,%1,%2,%3};"        \
                 : "+f"((c)[0]), "+f"((c)[1]), "+f"((c)[2]), "+f"((c)[3])       \
                 : "r"((a)[0]), "r"((a)[1]), "r"((a)[2]), "r"((a)[3]),          \
                   "r"((b)[0]), "r"((b)[1]))

#define CP16(dst, src)  asm volatile("cp.async.cg.shared.global [%0], [%1], 16;" :: "r"(dst), "l"(src))
#define CP_COMMIT()     asm volatile("cp.async.commit_group;" ::: "memory")
#define CP_WAIT1()      asm volatile("cp.async.wait_group 1;" ::: "memory")
#define CP_WAIT0()      asm volatile("cp.async.wait_group 0;" ::: "memory")

// convert float4 (row r, cols 4*c4..) into hi/lo fp16 smem tiles (stride SSTR)
__device__ __forceinline__ void cvt_store(char* smem, int hi, int lo,
                                          int r, int c4, float4 v) {
    uint32_t off = (uint32_t)(r * SSTR + c4 * 4) * 2u;
    float hx = __half2float(__float2half_rn(v.x));
    float hy = __half2float(__float2half_rn(v.y));
    float hz = __half2float(__float2half_rn(v.z));
    float hw = __half2float(__float2half_rn(v.w));
    *(uint2*)(smem + hi + off) = make_uint2(pack_h2(v.x, v.y), pack_h2(v.z, v.w));
    *(uint2*)(smem + lo + off) = make_uint2(pack_h2(v.x - hx, v.y - hy),
                                            pack_h2(v.z - hz, v.w - hw));
}

// async-load one 128x128 fp16 chunk into buffer at bufoff (128 threads)
__device__ __forceinline__ void load_chunk(uint32_t sb, uint32_t bufoff,
                                           const __half* src, size_t base, int tid) {
    #pragma unroll
    for (int i = 0; i < 16; i++) {
        int idx = tid + 128 * i;         // 0..2047
        int r = idx >> 4, c8 = idx & 15;
        uint32_t doff = (uint32_t)(r * (SSTR * 2) + c8 * 16);
        CP16(sb + bufoff + doff, src + base + (size_t)r * DN + c8 * 8);
    }
}

// QK chunk MMA: k16-outer, B hoisted across hi/lo chains (25% fewer LDSM)
__device__ __forceinline__ void mma_qk(uint32_t sb, uint32_t bufoff, int warp_n,
                                       int lane, float acc[2][4][4]) {
    const int ar = lane & 15, acs = (lane >> 4) << 3;
    const int br = (lane & 7) | ((lane >> 4) << 3), bcs = ((lane >> 3) & 1) << 3;
    const uint32_t ab[2] = {sb + OFF_QHI, sb + OFF_QLO};
    #pragma unroll
    for (int k16 = 0; k16 < 8; k16++) {
        const int kh = k16 * 16;
        uint32_t bf[4][2];
        #pragma unroll
        for (int p = 0; p < 2; p++) {
            uint32_t r0, r1, r2, r3;
            LDSM_X4(r0, r1, r2, r3,
                    sb + bufoff + (uint32_t)((warp_n + p * 16 + br) * SSTR + kh + bcs) * 2u);
            bf[2*p][0] = r0; bf[2*p][1] = r1;
            bf[2*p+1][0] = r2; bf[2*p+1][1] = r3;
        }
        #pragma unroll
        for (int ch = 0; ch < 2; ch++) {
            uint32_t a[2][4];
            #pragma unroll
            for (int mt = 0; mt < 2; mt++)
                LDSM_X4(a[mt][0], a[mt][1], a[mt][2], a[mt][3],
                        ab[ch] + (uint32_t)((mt * 16 + ar) * SSTR + kh + acs) * 2u);
            #pragma unroll
            for (int mt = 0; mt < 2; mt++)
                #pragma unroll
                for (int nt = 0; nt < 4; nt++) MMA_F16(acc[mt][nt], a[mt], bf[nt]);
        }
    }
}

// PV chunk MMA: k16-outer, trans-B hoisted across hi/lo chains
__device__ __forceinline__ void mma_pv(uint32_t sb, uint32_t bufoff, int warp_n,
                                       int lane, float acc[2][4][4]) {
    const int ar = lane & 15, acs = (lane >> 4) << 3;
    const int tkr = lane & 15, tnc = (lane >> 4) << 3;
    const uint32_t ab[2] = {sb + OFF_PHI, sb + OFF_PLO};
    #pragma unroll
    for (int k16 = 0; k16 < 8; k16++) {
        const int kh = k16 * 16;
        uint32_t bf[4][2];
        #pragma unroll
        for (int p = 0; p < 2; p++) {
            uint32_t r0, r1, r2, r3;
            LDSM_X4_T(r0, r1, r2, r3,
                      sb + bufoff + (uint32_t)((kh + tkr) * SSTR + warp_n + p * 16 + tnc) * 2u);
            bf[2*p][0] = r0; bf[2*p][1] = r1;
            bf[2*p+1][0] = r2; bf[2*p+1][1] = r3;
        }
        #pragma unroll
        for (int ch = 0; ch < 2; ch++) {
            uint32_t a[2][4];
            #pragma unroll
            for (int mt = 0; mt < 2; mt++)
                LDSM_X4(a[mt][0], a[mt][1], a[mt][2], a[mt][3],
                        ab[ch] + (uint32_t)((mt * 16 + ar) * SSTR + kh + acs) * 2u);
            #pragma unroll
            for (int mt = 0; mt < 2; mt++)
                #pragma unroll
                for (int nt = 0; nt < 4; nt++) MMA_F16(acc[mt][nt], a[mt], bf[nt]);
        }
    }
}

// ---------------------------------------------------------------------------
// prep: K,V fp32 -> fp16 global scratch (single rounding)
// ---------------------------------------------------------------------------
__global__ __launch_bounds__(256) void prep_kernel(const float* __restrict__ K,
                                                   const float* __restrict__ V)
{
    size_t i4 = (size_t)blockIdx.x * 256 + threadIdx.x;
    const float* src = blockIdx.y ? V : K;
    __half* dst = blockIdx.y ? g_Vh : g_Kh;
    float4 v = ((const float4*)src)[i4];
    ((uint2*)dst)[i4] = make_uint2(pack_h2(v.x, v.y), pack_h2(v.z, v.w));
}

// ---------------------------------------------------------------------------
// rel: g_Srel[b,q',k'] = dot(R[b,q',k',:], Q[b,448+q',:])  (streaming loads)
// ---------------------------------------------------------------------------
__global__ __launch_bounds__(256) void rel_kernel(const float* __restrict__ Q,
                                                  const float* __restrict__ R)
{
    __shared__ float qrow[DN];
    const int b  = blockIdx.x >> 6;
    const int qp = blockIdx.x & 63;
    const int tid = threadIdx.x;

    if (tid < 32)
        ((float4*)qrow)[tid] =
            *(const float4*)(Q + ((size_t)b * LN + (LN - LQN) + qp) * DN + tid * 4);
    __syncthreads();

    const int w = tid >> 5, lane = tid & 31;
    const float4 qv = ((const float4*)qrow)[lane];

    #pragma unroll
    for (int i = 0; i < 8; i++) {
        int kp = w + i * 8;
        const float4* rp = (const float4*)(R + (((size_t)b * LQN + qp) * LQN + kp) * DN);
        float4 rv = __ldcs(&rp[lane]);            // single-use stream; keep L2 for K/V
        float s = rv.x * qv.x + rv.y * qv.y + rv.z * qv.z + rv.w * qv.w;
        #pragma unroll
        for (int o = 16; o; o >>= 1) s += __shfl_xor_sync(0xffffffffu, s, o);
        if (lane == 0)
            g_Srel[((size_t)b * LQN + qp) * LQN + kp] = s;
    }
}

// ---------------------------------------------------------------------------
// fused: 128 threads, 4 warps, q-tile 32, m32 x n32 warp tiles, double-buffered B
// ---------------------------------------------------------------------------
__global__ __launch_bounds__(128, 2) void fused_attn(const float* __restrict__ Q,
                                                     const float* __restrict__ Mask,
                                                     float* __restrict__ attn,
                                                     float* __restrict__ out,
                                                     int qt_off)
{
    extern __shared__ char smem[];
    const int tid = threadIdx.x, wid = tid >> 5, lane = tid & 31;
    const uint32_t sb = smem_u32(smem);
    const int b = blockIdx.y, qt = blockIdx.x + qt_off;
    const size_t bkv = (size_t)b * LN * DN;
    const uint32_t buf[2] = {OFF_B0, OFF_B1};

    // prologue: K0 -> buf0, K1 -> buf1
    load_chunk(sb, OFF_B0, g_Kh, bkv, tid);
    CP_COMMIT();
    load_chunk(sb, OFF_B1, g_Kh, bkv + 128 * DN, tid);
    CP_COMMIT();

    {
        float* sm = (float*)(smem + OFF_MASK);
        #pragma unroll
        for (int i = 0; i < 4; i++) {
            int idx = tid + 128 * i;
            float m = Mask[(size_t)b * LN + idx];
            sm[idx] = (m != 0.f) ? logf(1.f - m) : 0.f;
        }
    }
    {
        const float* Qg = Q + ((size_t)b * LN + qt * 32) * DN;
        #pragma unroll
        for (int i = 0; i < 8; i++) {
            int idx = tid + 128 * i;
            int r = idx >> 5, c4 = idx & 31;
            cvt_store(smem, OFF_QHI, OFF_QLO, r, c4, *(const float4*)(Qg + r * DN + c4 * 4));
        }
    }

    const int warp_n = wid * 32;
    const int rq = lane >> 2, cq = (lane & 3) * 2;

    float accS[4][2][4][4];
    #pragma unroll
    for (int kb = 0; kb < 4; kb++)
        #pragma unroll
        for (int mt = 0; mt < 2; mt++)
            #pragma unroll
            for (int nt = 0; nt < 4; nt++)
                #pragma unroll
                for (int j = 0; j < 4; j++) accS[kb][mt][nt][j] = 0.f;

    // ---- QK: stage s computes chunk s from buf[s&1], prefetches s+2 (K2,K3,V0,V1) ----
    #pragma unroll
    for (int s = 0; s < 4; s++) {
        CP_WAIT1();
        __syncthreads();
        mma_qk(sb, buf[s & 1], warp_n, lane, accS[s]);
        __syncthreads();
        if (s < 2) load_chunk(sb, buf[s & 1], g_Kh, bkv + (size_t)(s + 2) * 128 * DN, tid);
        else       load_chunk(sb, buf[s & 1], g_Vh, bkv + (size_t)(s - 2) * 128 * DN, tid);
        CP_COMMIT();
    }

    // ---- rel add: rows 448.. (qt>=14), cols 448.. (chunk 3, warps 2,3) ----
    if (qt >= 14 && wid >= 2) {
        const int qp0 = (qt - 14) * 32;
        #pragma unroll
        for (int mt = 0; mt < 2; mt++) {
            const int row0 = qp0 + mt * 16 + rq;
            #pragma unroll
            for (int nt = 0; nt < 4; nt++) {
                int kp = (wid - 2) * 32 + nt * 8 + cq;
                float2 s0 = *(const float2*)&g_Srel[((size_t)b * LQN + row0) * LQN + kp];
                float2 s1 = *(const float2*)&g_Srel[((size_t)b * LQN + row0 + 8) * LQN + kp];
                accS[3][mt][nt][0] += s0.x; accS[3][mt][nt][1] += s0.y;
                accS[3][mt][nt][2] += s1.x; accS[3][mt][nt][3] += s1.y;
            }
        }
    }

    // ---- scale + mask + row max ----
    const float* sm = (const float*)(smem + OFF_MASK);
    float mx[2][2];
    mx[0][0] = mx[0][1] = mx[1][0] = mx[1][1] = -1e30f;
    #pragma unroll
    for (int kb = 0; kb < 4; kb++)
        #pragma unroll
        for (int mt = 0; mt < 2; mt++)
            #pragma unroll
            for (int nt = 0; nt < 4; nt++) {
                int c = kb * 128 + warp_n + nt * 8 + cq;
                float ml0 = sm[c], ml1 = sm[c + 1];
                float* a = accS[kb][mt][nt];
                a[0] = fmaf(a[0], INV_SQRT_D, ml0);
                a[1] = fmaf(a[1], INV_SQRT_D, ml1);
                a[2] = fmaf(a[2], INV_SQRT_D, ml0);
                a[3] = fmaf(a[3], INV_SQRT_D, ml1);
                mx[mt][0] = fmaxf(mx[mt][0], fmaxf(a[0], a[1]));
                mx[mt][1] = fmaxf(mx[mt][1], fmaxf(a[2], a[3]));
            }
    #pragma unroll
    for (int mt = 0; mt < 2; mt++)
        #pragma unroll
        for (int h = 0; h < 2; h++) {
            mx[mt][h] = fmaxf(mx[mt][h], __shfl_xor_sync(0xffffffffu, mx[mt][h], 1));
            mx[mt][h] = fmaxf(mx[mt][h], __shfl_xor_sync(0xffffffffu, mx[mt][h], 2));
        }
    float* rmax = (float*)(smem + OFF_RMAX);
    if ((lane & 3) == 0)
        #pragma unroll
        for (int mt = 0; mt < 2; mt++)
            #pragma unroll
            for (int h = 0; h < 2; h++)
                rmax[(mt * 16 + h * 8 + rq) * 4 + wid] = mx[mt][h];
    __syncthreads();
    #pragma unroll
    for (int mt = 0; mt < 2; mt++)
        #pragma unroll
        for (int h = 0; h < 2; h++) {
            const float* r4 = &rmax[(mt * 16 + h * 8 + rq) * 4];
            mx[mt][h] = fmaxf(fmaxf(r4[0], r4[1]), fmaxf(r4[2], r4[3]));
        }

    // ---- exp + row sum ----
    float sum[2][2] = {{0.f, 0.f}, {0.f, 0.f}};
    #pragma unroll
    for (int kb = 0; kb < 4; kb++)
        #pragma unroll
        for (int mt = 0; mt < 2; mt++)
            #pragma unroll
            for (int nt = 0; nt < 4; nt++) {
                float* a = accS[kb][mt][nt];
                a[0] = __expf(a[0] - mx[mt][0]); a[1] = __expf(a[1] - mx[mt][0]);
                a[2] = __expf(a[2] - mx[mt][1]); a[3] = __expf(a[3] - mx[mt][1]);
                sum[mt][0] += a[0] + a[1]; sum[mt][1] += a[2] + a[3];
            }
    #pragma unroll
    for (int mt = 0; mt < 2; mt++)
        #pragma unroll
        for (int h = 0; h < 2; h++) {
            sum[mt][h] += __shfl_xor_sync(0xffffffffu, sum[mt][h], 1);
            sum[mt][h] += __shfl_xor_sync(0xffffffffu, sum[mt][h], 2);
        }
    float* rsum = (float*)(smem + OFF_RSUM);
    if ((lane & 3) == 0)
        #pragma unroll
        for (int mt = 0; mt < 2; mt++)
            #pragma unroll
            for (int h = 0; h < 2; h++)
                rsum[(mt * 16 + h * 8 + rq) * 4 + wid] = sum[mt][h];
    __syncthreads();
    float inv[2][2];
    #pragma unroll
    for (int mt = 0; mt < 2; mt++)
        #pragma unroll
        for (int h = 0; h < 2; h++) {
            const float* r4 = &rsum[(mt * 16 + h * 8 + rq) * 4];
            inv[mt][h] = 1.f / (r4[0] + r4[1] + r4[2] + r4[3]);
        }

    // ---- normalize + write attn (streaming stores: single-use data) ----
    float* attnB = attn + ((size_t)b * LN + qt * 32) * LN;
    #pragma unroll
    for (int kb = 0; kb < 4; kb++)
        #pragma unroll
        for (int mt = 0; mt < 2; mt++) {
            const int r0 = mt * 16 + rq, r1 = r0 + 8;
            #pragma unroll
            for (int nt = 0; nt < 4; nt++) {
                int c = kb * 128 + warp_n + nt * 8 + cq;
                float* a = accS[kb][mt][nt];
                a[0] *= inv[mt][0]; a[1] *= inv[mt][0];
                a[2] *= inv[mt][1]; a[3] *= inv[mt][1];
                __stcs((float2*)(attnB + (size_t)r0 * LN + c), make_float2(a[0], a[1]));
                __stcs((float2*)(attnB + (size_t)r1 * LN + c), make_float2(a[2], a[3]));
            }
        }

    // ---- PV: stage s computes chunk s from buf[s&1], prefetches V s+2 ----
    float accO[2][4][4];
    #pragma unroll
    for (int mt = 0; mt < 2; mt++)
        #pragma unroll
        for (int nt = 0; nt < 4; nt++)
            #pragma unroll
            for (int j = 0; j < 4; j++) accO[mt][nt][j] = 0.f;

    #pragma unroll
    for (int s = 0; s < 4; s++) {
        // P chunk s -> fp16 hi/lo smem
        #pragma unroll
        for (int mt = 0; mt < 2; mt++) {
            const int r0 = mt * 16 + rq, r1 = r0 + 8;
            #pragma unroll
            for (int nt = 0; nt < 4; nt++) {
                int c = warp_n + nt * 8 + cq;
                const float* a = accS[s][mt][nt];
                float h0 = __half2float(__float2half_rn(a[0]));
                float h1 = __half2float(__float2half_rn(a[1]));
                float h2 = __half2float(__float2half_rn(a[2]));
                float h3 = __half2float(__float2half_rn(a[3]));
                uint32_t o0 = (uint32_t)(r0 * SSTR + c) * 2u;
                uint32_t o1 = (uint32_t)(r1 * SSTR + c) * 2u;
                *(uint32_t*)(smem + OFF_PHI + o0) = pack_h2(a[0], a[1]);
                *(uint32_t*)(smem + OFF_PLO + o0) = pack_h2(a[0] - h0, a[1] - h1);
                *(uint32_t*)(smem + OFF_PHI + o1) = pack_h2(a[2], a[3]);
                *(uint32_t*)(smem + OFF_PLO + o1) = pack_h2(a[2] - h2, a[3] - h3);
            }
        }
        if (s < 3) { CP_WAIT1(); } else { CP_WAIT0(); }
        __syncthreads();
        mma_pv(sb, buf[s & 1], warp_n, lane, accO);
        __syncthreads();
        if (s < 2) {
            load_chunk(sb, buf[s & 1], g_Vh, bkv + (size_t)(s + 2) * 128 * DN, tid);
            CP_COMMIT();
        }
    }

    // ---- write out ----
    float* Og = out + ((size_t)b * LN + qt * 32) * DN;
    #pragma unroll
    for (int mt = 0; mt < 2; mt++) {
        const int r0 = mt * 16 + rq, r1 = r0 + 8;
        #pragma unroll
        for (int nt = 0; nt < 4; nt++) {
            int c = warp_n + nt * 8 + cq;
            __stcs((float2*)(Og + (size_t)r0 * DN + c), make_float2(accO[mt][nt][0], accO[mt][nt][1]));
            __stcs((float2*)(Og + (size_t)r1 * DN + c), make_float2(accO[mt][nt][2], accO[mt][nt][3]));
        }
    }
}

// ---------------------------------------------------------------------------
extern "C" void kernel_launch(void* const* d_in, const int* in_sizes, int n_in,
                              void* d_out, int out_size)
{
    const float* Q  = (const float*)d_in[0];
    const float* K  = (const float*)d_in[1];
    const float* V  = (const float*)d_in[2];
    const float* R  = (const float*)d_in[3];
    const float* M  = (const float*)d_in[4];

    float* out  = (float*)d_out;                       // [128,512,128]
    float* attn = out + (size_t)BHN * LN * DN;         // [128,512,512]

    static cudaStream_t s1;
    static cudaEvent_t evFork, evPrep, evF2;
    static bool init_done = false;
    if (!init_done) {
        cudaFuncSetAttribute(fused_attn, cudaFuncAttributeMaxDynamicSharedMemorySize, SMEM_T);
        cudaStreamCreateWithFlags(&s1, cudaStreamNonBlocking);
        cudaEventCreateWithFlags(&evFork, cudaEventDisableTiming);
        cudaEventCreateWithFlags(&evPrep, cudaEventDisableTiming);
        cudaEventCreateWithFlags(&evF2, cudaEventDisableTiming);
        init_done = true;
    }

    // fork: rel on s1, concurrent with prep on main
    cudaEventRecord(evFork, 0);
    cudaStreamWaitEvent(s1, evFork, 0);
    rel_kernel<<<BHN * LQN, 256, 0, s1>>>(Q, R);       // 8192 blocks, DRAM-bound

    dim3 gprep((BHN * LN * DN) / 4 / 256, 2);          // (8192, 2)
    prep_kernel<<<gprep, 256>>>(K, V);
    cudaEventRecord(evPrep, 0);

    // s1: fused₂ (qt 14,15) right after {rel, prep} — overlaps with fused₁
    cudaStreamWaitEvent(s1, evPrep, 0);
    dim3 g2(2, BHN);
    fused_attn<<<g2, 128, SMEM_T, s1>>>(Q, M, attn, out, 14);
    cudaEventRecord(evF2, s1);

    // main: fused₁ (qt 0..13)
    dim3 g1(14, BHN);
    fused_attn<<<g1, 128, SMEM_T>>>(Q, M, attn, out, 0);

    // join
    cudaStreamWaitEvent(0, evF2, 0);
}

// round 14
// speedup vs baseline: 1.7044x; 1.1628x over previous
#include <cuda_runtime.h>
#include <cuda_fp16.h>
#include <cstdint>

#define BHN 128
#define LN  512
#define DN  128
#define LQN 64
#define INV_SQRT_D 0.08838834764831843f

#define SSTR 136
#define OFF_QH   0
#define OFF_B0   8704
#define OFF_B1   43520
#define OFF_PH   78336
#define OFF_MASK 87040
#define OFF_RMAX 89088
#define OFF_RSUM 89600
#define SMEM_T   90112

__device__ float g_Srel[(size_t)BHN * LQN * LQN];        // 2 MB
__device__ __half g_Kh[(size_t)BHN * LN * DN];           // 16 MB
__device__ __half g_Vh[(size_t)BHN * LN * DN];           // 16 MB

__device__ __forceinline__ uint32_t smem_u32(const void* p) {
    uint32_t a;
    asm("{ .reg .u64 t; cvta.to.shared.u64 t, %1; cvt.u32.u64 %0, t; }" : "=r"(a) : "l"(p));
    return a;
}
__device__ __forceinline__ uint32_t pack_h2(float a, float b) {
    __half2 h = __floats2half2_rn(a, b);    // .x = a (low half)
    return *(uint32_t*)&h;
}

#define LDSM_X4(r0, r1, r2, r3, addr)                                           \
    asm volatile("ldmatrix.sync.aligned.m8n8.x4.shared.b16 {%0,%1,%2,%3}, [%4];"\
                 : "=r"(r0), "=r"(r1), "=r"(r2), "=r"(r3) : "r"(addr))
#define LDSM_X4_T(r0, r1, r2, r3, addr)                                         \
    asm volatile("ldmatrix.sync.aligned.m8n8.x4.trans.shared.b16 {%0,%1,%2,%3}, [%4];"\
                 : "=r"(r0), "=r"(r1), "=r"(r2), "=r"(r3) : "r"(addr))
#define MMA_F16(c, a, b)                                                        \
    asm volatile("mma.sync.aligned.m16n8k16.row.col.f32.f16.f16.f32 "           \
                 "{%0,%1,%2,%3}, {%4,%5,%6,%7}, {%8,%9}, {%0,%1,%2,%3};"        \
                 : "+f"((c)[0]), "+f"((c)[1]), "+f"((c)[2]), "+f"((c)[3])       \
                 : "r"((a)[0]), "r"((a)[1]), "r"((a)[2]), "r"((a)[3]),          \
                   "r"((b)[0]), "r"((b)[1]))

#define CP16(dst, src)  asm volatile("cp.async.cg.shared.global [%0], [%1], 16;" :: "r"(dst), "l"(src))
#define CP_COMMIT()     asm volatile("cp.async.commit_group;" ::: "memory")
#define CP_WAIT1()      asm volatile("cp.async.wait_group 1;" ::: "memory")
#define CP_WAIT0()      asm volatile("cp.async.wait_group 0;" ::: "memory")

// convert float4 (row r, cols 4*c4..) into a single fp16 smem tile (stride SSTR)
__device__ __forceinline__ void cvt_store1(char* smem, int off, int r, int c4, float4 v) {
    uint32_t o = (uint32_t)(r * SSTR + c4 * 4) * 2u;
    *(uint2*)(smem + off + o) = make_uint2(pack_h2(v.x, v.y), pack_h2(v.z, v.w));
}

// async-load one 128x128 fp16 chunk into buffer at bufoff (128 threads)
__device__ __forceinline__ void load_chunk(uint32_t sb, uint32_t bufoff,
                                           const __half* src, size_t base, int tid) {
    #pragma unroll
    for (int i = 0; i < 16; i++) {
        int idx = tid + 128 * i;         // 0..2047
        int r = idx >> 4, c8 = idx & 15;
        uint32_t doff = (uint32_t)(r * (SSTR * 2) + c8 * 16);
        CP16(sb + bufoff + doff, src + base + (size_t)r * DN + c8 * 8);
    }
}

// QK chunk MMA: single fp16 chain, m32 x n32 warp tile
__device__ __forceinline__ void mma_qk(uint32_t sb, uint32_t bufoff, int warp_n,
                                       int lane, float acc[2][4][4]) {
    const int ar = lane & 15, acs = (lane >> 4) << 3;
    const int br = (lane & 7) | ((lane >> 4) << 3), bcs = ((lane >> 3) & 1) << 3;
    #pragma unroll
    for (int k16 = 0; k16 < 8; k16++) {
        const int kh = k16 * 16;
        uint32_t bf[4][2];
        #pragma unroll
        for (int p = 0; p < 2; p++) {
            uint32_t r0, r1, r2, r3;
            LDSM_X4(r0, r1, r2, r3,
                    sb + bufoff + (uint32_t)((warp_n + p * 16 + br) * SSTR + kh + bcs) * 2u);
            bf[2*p][0] = r0; bf[2*p][1] = r1;
            bf[2*p+1][0] = r2; bf[2*p+1][1] = r3;
        }
        uint32_t a[2][4];
        #pragma unroll
        for (int mt = 0; mt < 2; mt++)
            LDSM_X4(a[mt][0], a[mt][1], a[mt][2], a[mt][3],
                    sb + OFF_QH + (uint32_t)((mt * 16 + ar) * SSTR + kh + acs) * 2u);
        #pragma unroll
        for (int mt = 0; mt < 2; mt++)
            #pragma unroll
            for (int nt = 0; nt < 4; nt++) MMA_F16(acc[mt][nt], a[mt], bf[nt]);
    }
}

// PV chunk MMA: single fp16 chain, B via ldmatrix.trans
__device__ __forceinline__ void mma_pv(uint32_t sb, uint32_t bufoff, int warp_n,
                                       int lane, float acc[2][4][4]) {
    const int ar = lane & 15, acs = (lane >> 4) << 3;
    const int tkr = lane & 15, tnc = (lane >> 4) << 3;
    #pragma unroll
    for (int k16 = 0; k16 < 8; k16++) {
        const int kh = k16 * 16;
        uint32_t bf[4][2];
        #pragma unroll
        for (int p = 0; p < 2; p++) {
            uint32_t r0, r1, r2, r3;
            LDSM_X4_T(r0, r1, r2, r3,
                      sb + bufoff + (uint32_t)((kh + tkr) * SSTR + warp_n + p * 16 + tnc) * 2u);
            bf[2*p][0] = r0; bf[2*p][1] = r1;
            bf[2*p+1][0] = r2; bf[2*p+1][1] = r3;
        }
        uint32_t a[2][4];
        #pragma unroll
        for (int mt = 0; mt < 2; mt++)
            LDSM_X4(a[mt][0], a[mt][1], a[mt][2], a[mt][3],
                    sb + OFF_PH + (uint32_t)((mt * 16 + ar) * SSTR + kh + acs) * 2u);
        #pragma unroll
        for (int mt = 0; mt < 2; mt++)
            #pragma unroll
            for (int nt = 0; nt < 4; nt++) MMA_F16(acc[mt][nt], a[mt], bf[nt]);
    }
}

// ---------------------------------------------------------------------------
// prep: K,V fp32 -> fp16 global scratch (single rounding)
// ---------------------------------------------------------------------------
__global__ __launch_bounds__(256) void prep_kernel(const float* __restrict__ K,
                                                   const float* __restrict__ V)
{
    size_t i4 = (size_t)blockIdx.x * 256 + threadIdx.x;
    const float* src = blockIdx.y ? V : K;
    __half* dst = blockIdx.y ? g_Vh : g_Kh;
    float4 v = ((const float4*)src)[i4];
    ((uint2*)dst)[i4] = make_uint2(pack_h2(v.x, v.y), pack_h2(v.z, v.w));
}

// ---------------------------------------------------------------------------
// rel: g_Srel[b,q',k'] = dot(R[b,q',k',:], Q[b,448+q',:])  (streaming loads)
// ---------------------------------------------------------------------------
__global__ __launch_bounds__(256) void rel_kernel(const float* __restrict__ Q,
                                                  const float* __restrict__ R)
{
    __shared__ float qrow[DN];
    const int b  = blockIdx.x >> 6;
    const int qp = blockIdx.x & 63;
    const int tid = threadIdx.x;

    if (tid < 32)
        ((float4*)qrow)[tid] =
            *(const float4*)(Q + ((size_t)b * LN + (LN - LQN) + qp) * DN + tid * 4);
    __syncthreads();

    const int w = tid >> 5, lane = tid & 31;
    const float4 qv = ((const float4*)qrow)[lane];

    #pragma unroll
    for (int i = 0; i < 8; i++) {
        int kp = w + i * 8;
        const float4* rp = (const float4*)(R + (((size_t)b * LQN + qp) * LQN + kp) * DN);
        float4 rv = __ldcs(&rp[lane]);            // single-use stream; keep L2 for K/V
        float s = rv.x * qv.x + rv.y * qv.y + rv.z * qv.z + rv.w * qv.w;
        #pragma unroll
        for (int o = 16; o; o >>= 1) s += __shfl_xor_sync(0xffffffffu, s, o);
        if (lane == 0)
            g_Srel[((size_t)b * LQN + qp) * LQN + kp] = s;
    }
}

// ---------------------------------------------------------------------------
// fused: 128 threads, 4 warps, q-tile 32, m32 x n32, single-chain fp16
// ---------------------------------------------------------------------------
__global__ __launch_bounds__(128, 2) void fused_attn(const float* __restrict__ Q,
                                                     const float* __restrict__ Mask,
                                                     float* __restrict__ attn,
                                                     float* __restrict__ out,
                                                     int qt_off)
{
    extern __shared__ char smem[];
    const int tid = threadIdx.x, wid = tid >> 5, lane = tid & 31;
    const uint32_t sb = smem_u32(smem);
    const int b = blockIdx.y, qt = blockIdx.x + qt_off;
    const size_t bkv = (size_t)b * LN * DN;
    const uint32_t buf[2] = {OFF_B0, OFF_B1};

    // prologue: K0 -> buf0, K1 -> buf1
    load_chunk(sb, OFF_B0, g_Kh, bkv, tid);
    CP_COMMIT();
    load_chunk(sb, OFF_B1, g_Kh, bkv + 128 * DN, tid);
    CP_COMMIT();

    {
        float* sm = (float*)(smem + OFF_MASK);
        #pragma unroll
        for (int i = 0; i < 4; i++) {
            int idx = tid + 128 * i;
            float m = Mask[(size_t)b * LN + idx];
            sm[idx] = (m != 0.f) ? logf(1.f - m) : 0.f;
        }
    }
    {
        const float* Qg = Q + ((size_t)b * LN + qt * 32) * DN;
        #pragma unroll
        for (int i = 0; i < 8; i++) {
            int idx = tid + 128 * i;
            int r = idx >> 5, c4 = idx & 31;
            cvt_store1(smem, OFF_QH, r, c4, *(const float4*)(Qg + r * DN + c4 * 4));
        }
    }

    const int warp_n = wid * 32;
    const int rq = lane >> 2, cq = (lane & 3) * 2;

    float accS[4][2][4][4];
    #pragma unroll
    for (int kb = 0; kb < 4; kb++)
        #pragma unroll
        for (int mt = 0; mt < 2; mt++)
            #pragma unroll
            for (int nt = 0; nt < 4; nt++)
                #pragma unroll
                for (int j = 0; j < 4; j++) accS[kb][mt][nt][j] = 0.f;

    // ---- QK: stage s computes chunk s from buf[s&1], prefetches s+2 (K2,K3,V0,V1) ----
    #pragma unroll
    for (int s = 0; s < 4; s++) {
        CP_WAIT1();
        __syncthreads();
        mma_qk(sb, buf[s & 1], warp_n, lane, accS[s]);
        __syncthreads();
        if (s < 2) load_chunk(sb, buf[s & 1], g_Kh, bkv + (size_t)(s + 2) * 128 * DN, tid);
        else       load_chunk(sb, buf[s & 1], g_Vh, bkv + (size_t)(s - 2) * 128 * DN, tid);
        CP_COMMIT();
    }

    // ---- rel add: rows 448.. (qt>=14), cols 448.. (chunk 3, warps 2,3) ----
    if (qt >= 14 && wid >= 2) {
        const int qp0 = (qt - 14) * 32;
        #pragma unroll
        for (int mt = 0; mt < 2; mt++) {
            const int row0 = qp0 + mt * 16 + rq;
            #pragma unroll
            for (int nt = 0; nt < 4; nt++) {
                int kp = (wid - 2) * 32 + nt * 8 + cq;
                float2 s0 = *(const float2*)&g_Srel[((size_t)b * LQN + row0) * LQN + kp];
                float2 s1 = *(const float2*)&g_Srel[((size_t)b * LQN + row0 + 8) * LQN + kp];
                accS[3][mt][nt][0] += s0.x; accS[3][mt][nt][1] += s0.y;
                accS[3][mt][nt][2] += s1.x; accS[3][mt][nt][3] += s1.y;
            }
        }
    }

    // ---- scale + mask + row max ----
    const float* sm = (const float*)(smem + OFF_MASK);
    float mx[2][2];
    mx[0][0] = mx[0][1] = mx[1][0] = mx[1][1] = -1e30f;
    #pragma unroll
    for (int kb = 0; kb < 4; kb++)
        #pragma unroll
        for (int mt = 0; mt < 2; mt++)
            #pragma unroll
            for (int nt = 0; nt < 4; nt++) {
                int c = kb * 128 + warp_n + nt * 8 + cq;
                float ml0 = sm[c], ml1 = sm[c + 1];
                float* a = accS[kb][mt][nt];
                a[0] = fmaf(a[0], INV_SQRT_D, ml0);
                a[1] = fmaf(a[1], INV_SQRT_D, ml1);
                a[2] = fmaf(a[2], INV_SQRT_D, ml0);
                a[3] = fmaf(a[3], INV_SQRT_D, ml1);
                mx[mt][0] = fmaxf(mx[mt][0], fmaxf(a[0], a[1]));
                mx[mt][1] = fmaxf(mx[mt][1], fmaxf(a[2], a[3]));
            }
    #pragma unroll
    for (int mt = 0; mt < 2; mt++)
        #pragma unroll
        for (int h = 0; h < 2; h++) {
            mx[mt][h] = fmaxf(mx[mt][h], __shfl_xor_sync(0xffffffffu, mx[mt][h], 1));
            mx[mt][h] = fmaxf(mx[mt][h], __shfl_xor_sync(0xffffffffu, mx[mt][h], 2));
        }
    float* rmax = (float*)(smem + OFF_RMAX);
    if ((lane & 3) == 0)
        #pragma unroll
        for (int mt = 0; mt < 2; mt++)
            #pragma unroll
            for (int h = 0; h < 2; h++)
                rmax[(mt * 16 + h * 8 + rq) * 4 + wid] = mx[mt][h];
    __syncthreads();
    #pragma unroll
    for (int mt = 0; mt < 2; mt++)
        #pragma unroll
        for (int h = 0; h < 2; h++) {
            const float* r4 = &rmax[(mt * 16 + h * 8 + rq) * 4];
            mx[mt][h] = fmaxf(fmaxf(r4[0], r4[1]), fmaxf(r4[2], r4[3]));
        }

    // ---- exp + row sum ----
    float sum[2][2] = {{0.f, 0.f}, {0.f, 0.f}};
    #pragma unroll
    for (int kb = 0; kb < 4; kb++)
        #pragma unroll
        for (int mt = 0; mt < 2; mt++)
            #pragma unroll
            for (int nt = 0; nt < 4; nt++) {
                float* a = accS[kb][mt][nt];
                a[0] = __expf(a[0] - mx[mt][0]); a[1] = __expf(a[1] - mx[mt][0]);
                a[2] = __expf(a[2] - mx[mt][1]); a[3] = __expf(a[3] - mx[mt][1]);
                sum[mt][0] += a[0] + a[1]; sum[mt][1] += a[2] + a[3];
            }
    #pragma unroll
    for (int mt = 0; mt < 2; mt++)
        #pragma unroll
        for (int h = 0; h < 2; h++) {
            sum[mt][h] += __shfl_xor_sync(0xffffffffu, sum[mt][h], 1);
            sum[mt][h] += __shfl_xor_sync(0xffffffffu, sum[mt][h], 2);
        }
    float* rsum = (float*)(smem + OFF_RSUM);
    if ((lane & 3) == 0)
        #pragma unroll
        for (int mt = 0; mt < 2; mt++)
            #pragma unroll
            for (int h = 0; h < 2; h++)
                rsum[(mt * 16 + h * 8 + rq) * 4 + wid] = sum[mt][h];
    __syncthreads();
    float inv[2][2];
    #pragma unroll
    for (int mt = 0; mt < 2; mt++)
        #pragma unroll
        for (int h = 0; h < 2; h++) {
            const float* r4 = &rsum[(mt * 16 + h * 8 + rq) * 4];
            inv[mt][h] = 1.f / (r4[0] + r4[1] + r4[2] + r4[3]);
        }

    // ---- normalize + write attn (streaming stores) + stage P chunk later ----
    float* attnB = attn + ((size_t)b * LN + qt * 32) * LN;
    #pragma unroll
    for (int kb = 0; kb < 4; kb++)
        #pragma unroll
        for (int mt = 0; mt < 2; mt++) {
            const int r0 = mt * 16 + rq, r1 = r0 + 8;
            #pragma unroll
            for (int nt = 0; nt < 4; nt++) {
                int c = kb * 128 + warp_n + nt * 8 + cq;
                float* a = accS[kb][mt][nt];
                a[0] *= inv[mt][0]; a[1] *= inv[mt][0];
                a[2] *= inv[mt][1]; a[3] *= inv[mt][1];
                __stcs((float2*)(attnB + (size_t)r0 * LN + c), make_float2(a[0], a[1]));
                __stcs((float2*)(attnB + (size_t)r1 * LN + c), make_float2(a[2], a[3]));
            }
        }

    // ---- PV: stage s computes chunk s from buf[s&1], prefetches V s+2 ----
    float accO[2][4][4];
    #pragma unroll
    for (int mt = 0; mt < 2; mt++)
        #pragma unroll
        for (int nt = 0; nt < 4; nt++)
            #pragma unroll
            for (int j = 0; j < 4; j++) accO[mt][nt][j] = 0.f;

    #pragma unroll
    for (int s = 0; s < 4; s++) {
        // P chunk s -> fp16 smem (single rounding)
        #pragma unroll
        for (int mt = 0; mt < 2; mt++) {
            const int r0 = mt * 16 + rq, r1 = r0 + 8;
            #pragma unroll
            for (int nt = 0; nt < 4; nt++) {
                int c = warp_n + nt * 8 + cq;
                const float* a = accS[s][mt][nt];
                *(uint32_t*)(smem + OFF_PH + (uint32_t)(r0 * SSTR + c) * 2u) = pack_h2(a[0], a[1]);
                *(uint32_t*)(smem + OFF_PH + (uint32_t)(r1 * SSTR + c) * 2u) = pack_h2(a[2], a[3]);
            }
        }
        if (s < 3) { CP_WAIT1(); } else { CP_WAIT0(); }
        __syncthreads();
        mma_pv(sb, buf[s & 1], warp_n, lane, accO);
        __syncthreads();
        if (s < 2) {
            load_chunk(sb, buf[s & 1], g_Vh, bkv + (size_t)(s + 2) * 128 * DN, tid);
            CP_COMMIT();
        }
    }

    // ---- write out ----
    float* Og = out + ((size_t)b * LN + qt * 32) * DN;
    #pragma unroll
    for (int mt = 0; mt < 2; mt++) {
        const int r0 = mt * 16 + rq, r1 = r0 + 8;
        #pragma unroll
        for (int nt = 0; nt < 4; nt++) {
            int c = warp_n + nt * 8 + cq;
            __stcs((float2*)(Og + (size_t)r0 * DN + c), make_float2(accO[mt][nt][0], accO[mt][nt][1]));
            __stcs((float2*)(Og + (size_t)r1 * DN + c), make_float2(accO[mt][nt][2], accO[mt][nt][3]));
        }
    }
}

// ---------------------------------------------------------------------------
extern "C" void kernel_launch(void* const* d_in, const int* in_sizes, int n_in,
                              void* d_out, int out_size)
{
    const float* Q  = (const float*)d_in[0];
    const float* K  = (const float*)d_in[1];
    const float* V  = (const float*)d_in[2];
    const float* R  = (const float*)d_in[3];
    const float* M  = (const float*)d_in[4];

    float* out  = (float*)d_out;                       // [128,512,128]
    float* attn = out + (size_t)BHN * LN * DN;         // [128,512,512]

    static cudaStream_t s1;
    static cudaEvent_t evFork, evPrep, evF2;
    static bool init_done = false;
    if (!init_done) {
        cudaFuncSetAttribute(fused_attn, cudaFuncAttributeMaxDynamicSharedMemorySize, SMEM_T);
        cudaStreamCreateWithFlags(&s1, cudaStreamNonBlocking);
        cudaEventCreateWithFlags(&evFork, cudaEventDisableTiming);
        cudaEventCreateWithFlags(&evPrep, cudaEventDisableTiming);
        cudaEventCreateWithFlags(&evF2, cudaEventDisableTiming);
        init_done = true;
    }

    // fork: rel on s1, concurrent with prep on main
    cudaEventRecord(evFork, 0);
    cudaStreamWaitEvent(s1, evFork, 0);
    rel_kernel<<<BHN * LQN, 256, 0, s1>>>(Q, R);       // 8192 blocks, DRAM-bound

    dim3 gprep((BHN * LN * DN) / 4 / 256, 2);          // (8192, 2)
    prep_kernel<<<gprep, 256>>>(K, V);
    cudaEventRecord(evPrep, 0);

    // s1: fused₂ (qt 14,15) right after {rel, prep} — overlaps with fused₁
    cudaStreamWaitEvent(s1, evPrep, 0);
    dim3 g2(2, BHN);
    fused_attn<<<g2, 128, SMEM_T, s1>>>(Q, M, attn, out, 14);
    cudaEventRecord(evF2, s1);

    // main: fused₁ (qt 0..13)
    dim3 g1(14, BHN);
    fused_attn<<<g1, 128, SMEM_T>>>(Q, M, attn, out, 0);

    // join
    cudaStreamWaitEvent(0, evF2, 0);
}

// round 15
// speedup vs baseline: 1.7187x; 1.0084x over previous
#include <cuda_runtime.h>
#include <cuda_fp16.h>
#include <cstdint>

#define BHN 128
#define LN  512
#define DN  128
#define LQN 64
#define INV_SQRT_D 0.08838834764831843f

#define SSTR 136
#define OFF_QH   0
#define OFF_B0   8704
#define OFF_B1   43520
#define OFF_PH   78336
#define OFF_MASK 87040
#define OFF_RMAX 89088
#define OFF_RSUM 89600
#define SMEM_T   90112

__device__ float g_Srel[(size_t)BHN * LQN * LQN];        // 2 MB
__device__ __half g_Kh[(size_t)BHN * LN * DN];           // 16 MB
__device__ __half g_Vh[(size_t)BHN * LN * DN];           // 16 MB

__device__ __forceinline__ uint32_t smem_u32(const void* p) {
    uint32_t a;
    asm("{ .reg .u64 t; cvta.to.shared.u64 t, %1; cvt.u32.u64 %0, t; }" : "=r"(a) : "l"(p));
    return a;
}
__device__ __forceinline__ uint32_t pack_h2(float a, float b) {
    __half2 h = __floats2half2_rn(a, b);    // .x = a (low half)
    return *(uint32_t*)&h;
}

#define LDSM_X4(r0, r1, r2, r3, addr)                                           \
    asm volatile("ldmatrix.sync.aligned.m8n8.x4.shared.b16 {%0,%1,%2,%3}, [%4];"\
                 : "=r"(r0), "=r"(r1), "=r"(r2), "=r"(r3) : "r"(addr))
#define LDSM_X4_T(r0, r1, r2, r3, addr)                                         \
    asm volatile("ldmatrix.sync.aligned.m8n8.x4.trans.shared.b16 {%0,%1,%2,%3}, [%4];"\
                 : "=r"(r0), "=r"(r1), "=r"(r2), "=r"(r3) : "r"(addr))
#define MMA_F16(c, a, b)                                                        \
    asm volatile("mma.sync.aligned.m16n8k16.row.col.f32.f16.f16.f32 "           \
                 "{%0,%1,%2,%3}, {%4,%5,%6,%7}, {%8,%9}, {%0,%1,%2,%3};"        \
                 : "+f"((c)[0]), "+f"((c)[1]), "+f"((c)[2]), "+f"((c)[3])       \
                 : "r"((a)[0]), "r"((a)[1]), "r"((a)[2]), "r"((a)[3]),          \
                   "r"((b)[0]), "r"((b)[1]))

#define CP16(dst, src)  asm volatile("cp.async.cg.shared.global [%0], [%1], 16;" :: "r"(dst), "l"(src))
#define CP_COMMIT()     asm volatile("cp.async.commit_group;" ::: "memory")
#define CP_WAIT1()      asm volatile("cp.async.wait_group 1;" ::: "memory")
#define CP_WAIT0()      asm volatile("cp.async.wait_group 0;" ::: "memory")

// convert float4 (row r, cols 4*c4..) into a single fp16 smem tile (stride SSTR)
__device__ __forceinline__ void cvt_store1(char* smem, int off, int r, int c4, float4 v) {
    uint32_t o = (uint32_t)(r * SSTR + c4 * 4) * 2u;
    *(uint2*)(smem + off + o) = make_uint2(pack_h2(v.x, v.y), pack_h2(v.z, v.w));
}

// async-load one 128x128 fp16 chunk into buffer at bufoff (128 threads)
__device__ __forceinline__ void load_chunk(uint32_t sb, uint32_t bufoff,
                                           const __half* src, size_t base, int tid) {
    #pragma unroll
    for (int i = 0; i < 16; i++) {
        int idx = tid + 128 * i;         // 0..2047
        int r = idx >> 4, c8 = idx & 15;
        uint32_t doff = (uint32_t)(r * (SSTR * 2) + c8 * 16);
        CP16(sb + bufoff + doff, src + base + (size_t)r * DN + c8 * 8);
    }
}

// QK chunk MMA: single fp16 chain, m32 x n32 warp tile
__device__ __forceinline__ void mma_qk(uint32_t sb, uint32_t bufoff, int warp_n,
                                       int lane, float acc[2][4][4]) {
    const int ar = lane & 15, acs = (lane >> 4) << 3;
    const int br = (lane & 7) | ((lane >> 4) << 3), bcs = ((lane >> 3) & 1) << 3;
    #pragma unroll
    for (int k16 = 0; k16 < 8; k16++) {
        const int kh = k16 * 16;
        uint32_t bf[4][2];
        #pragma unroll
        for (int p = 0; p < 2; p++) {
            uint32_t r0, r1, r2, r3;
            LDSM_X4(r0, r1, r2, r3,
                    sb + bufoff + (uint32_t)((warp_n + p * 16 + br) * SSTR + kh + bcs) * 2u);
            bf[2*p][0] = r0; bf[2*p][1] = r1;
            bf[2*p+1][0] = r2; bf[2*p+1][1] = r3;
        }
        uint32_t a[2][4];
        #pragma unroll
        for (int mt = 0; mt < 2; mt++)
            LDSM_X4(a[mt][0], a[mt][1], a[mt][2], a[mt][3],
                    sb + OFF_QH + (uint32_t)((mt * 16 + ar) * SSTR + kh + acs) * 2u);
        #pragma unroll
        for (int mt = 0; mt < 2; mt++)
            #pragma unroll
            for (int nt = 0; nt < 4; nt++) MMA_F16(acc[mt][nt], a[mt], bf[nt]);
    }
}

// PV chunk MMA: single fp16 chain, B via ldmatrix.trans
__device__ __forceinline__ void mma_pv(uint32_t sb, uint32_t bufoff, int warp_n,
                                       int lane, float acc[2][4][4]) {
    const int ar = lane & 15, acs = (lane >> 4) << 3;
    const int tkr = lane & 15, tnc = (lane >> 4) << 3;
    #pragma unroll
    for (int k16 = 0; k16 < 8; k16++) {
        const int kh = k16 * 16;
        uint32_t bf[4][2];
        #pragma unroll
        for (int p = 0; p < 2; p++) {
            uint32_t r0, r1, r2, r3;
            LDSM_X4_T(r0, r1, r2, r3,
                      sb + bufoff + (uint32_t)((kh + tkr) * SSTR + warp_n + p * 16 + tnc) * 2u);
            bf[2*p][0] = r0; bf[2*p][1] = r1;
            bf[2*p+1][0] = r2; bf[2*p+1][1] = r3;
        }
        uint32_t a[2][4];
        #pragma unroll
        for (int mt = 0; mt < 2; mt++)
            LDSM_X4(a[mt][0], a[mt][1], a[mt][2], a[mt][3],
                    sb + OFF_PH + (uint32_t)((mt * 16 + ar) * SSTR + kh + acs) * 2u);
        #pragma unroll
        for (int mt = 0; mt < 2; mt++)
            #pragma unroll
            for (int nt = 0; nt < 4; nt++) MMA_F16(acc[mt][nt], a[mt], bf[nt]);
    }
}

// ---------------------------------------------------------------------------
// prep: K,V fp32 -> fp16 global scratch (single rounding)
// ---------------------------------------------------------------------------
__global__ __launch_bounds__(256) void prep_kernel(const float* __restrict__ K,
                                                   const float* __restrict__ V)
{
    size_t i4 = (size_t)blockIdx.x * 256 + threadIdx.x;
    const float* src = blockIdx.y ? V : K;
    __half* dst = blockIdx.y ? g_Vh : g_Kh;
    float4 v = ((const float4*)src)[i4];
    ((uint2*)dst)[i4] = make_uint2(pack_h2(v.x, v.y), pack_h2(v.z, v.w));
}

// ---------------------------------------------------------------------------
// rel: g_Srel[b,q',k'] = dot(R[b,q',k',:], Q[b,448+q',:])
// 128 threads / 4 warps (small reg footprint -> co-resident with fused_attn)
// ---------------------------------------------------------------------------
__global__ __launch_bounds__(128) void rel_kernel(const float* __restrict__ Q,
                                                  const float* __restrict__ R)
{
    __shared__ float qrow[DN];
    const int b  = blockIdx.x >> 6;
    const int qp = blockIdx.x & 63;
    const int tid = threadIdx.x;

    if (tid < 32)
        ((float4*)qrow)[tid] =
            *(const float4*)(Q + ((size_t)b * LN + (LN - LQN) + qp) * DN + tid * 4);
    __syncthreads();

    const int w = tid >> 5, lane = tid & 31;
    const float4 qv = ((const float4*)qrow)[lane];

    #pragma unroll
    for (int i = 0; i < 16; i++) {
        int kp = w + i * 4;
        const float4* rp = (const float4*)(R + (((size_t)b * LQN + qp) * LQN + kp) * DN);
        float4 rv = __ldcs(&rp[lane]);            // single-use stream; keep L2 for K/V
        float s = rv.x * qv.x + rv.y * qv.y + rv.z * qv.z + rv.w * qv.w;
        #pragma unroll
        for (int o = 16; o; o >>= 1) s += __shfl_xor_sync(0xffffffffu, s, o);
        if (lane == 0)
            g_Srel[((size_t)b * LQN + qp) * LQN + kp] = s;
    }
}

// ---------------------------------------------------------------------------
// fused: 128 threads, 4 warps, q-tile 32, m32 x n32, single-chain fp16
// ---------------------------------------------------------------------------
__global__ __launch_bounds__(128, 2) void fused_attn(const float* __restrict__ Q,
                                                     const float* __restrict__ Mask,
                                                     float* __restrict__ attn,
                                                     float* __restrict__ out,
                                                     int qt_off)
{
    extern __shared__ char smem[];
    const int tid = threadIdx.x, wid = tid >> 5, lane = tid & 31;
    const uint32_t sb = smem_u32(smem);
    const int b = blockIdx.y, qt = blockIdx.x + qt_off;
    const size_t bkv = (size_t)b * LN * DN;
    const uint32_t buf[2] = {OFF_B0, OFF_B1};

    // prologue: K0 -> buf0, K1 -> buf1
    load_chunk(sb, OFF_B0, g_Kh, bkv, tid);
    CP_COMMIT();
    load_chunk(sb, OFF_B1, g_Kh, bkv + 128 * DN, tid);
    CP_COMMIT();

    {
        float* sm = (float*)(smem + OFF_MASK);
        #pragma unroll
        for (int i = 0; i < 4; i++) {
            int idx = tid + 128 * i;
            float m = Mask[(size_t)b * LN + idx];
            sm[idx] = (m != 0.f) ? logf(1.f - m) : 0.f;
        }
    }
    {
        const float* Qg = Q + ((size_t)b * LN + qt * 32) * DN;
        #pragma unroll
        for (int i = 0; i < 8; i++) {
            int idx = tid + 128 * i;
            int r = idx >> 5, c4 = idx & 31;
            cvt_store1(smem, OFF_QH, r, c4, *(const float4*)(Qg + r * DN + c4 * 4));
        }
    }

    const int warp_n = wid * 32;
    const int rq = lane >> 2, cq = (lane & 3) * 2;

    float accS[4][2][4][4];
    #pragma unroll
    for (int kb = 0; kb < 4; kb++)
        #pragma unroll
        for (int mt = 0; mt < 2; mt++)
            #pragma unroll
            for (int nt = 0; nt < 4; nt++)
                #pragma unroll
                for (int j = 0; j < 4; j++) accS[kb][mt][nt][j] = 0.f;

    // ---- QK: stage s computes chunk s from buf[s&1], prefetches s+2 (K2,K3,V0,V1) ----
    #pragma unroll
    for (int s = 0; s < 4; s++) {
        CP_WAIT1();
        __syncthreads();
        mma_qk(sb, buf[s & 1], warp_n, lane, accS[s]);
        __syncthreads();
        if (s < 2) load_chunk(sb, buf[s & 1], g_Kh, bkv + (size_t)(s + 2) * 128 * DN, tid);
        else       load_chunk(sb, buf[s & 1], g_Vh, bkv + (size_t)(s - 2) * 128 * DN, tid);
        CP_COMMIT();
    }

    // ---- rel add: rows 448.. (qt>=14), cols 448.. (chunk 3, warps 2,3) ----
    if (qt >= 14 && wid >= 2) {
        const int qp0 = (qt - 14) * 32;
        #pragma unroll
        for (int mt = 0; mt < 2; mt++) {
            const int row0 = qp0 + mt * 16 + rq;
            #pragma unroll
            for (int nt = 0; nt < 4; nt++) {
                int kp = (wid - 2) * 32 + nt * 8 + cq;
                float2 s0 = *(const float2*)&g_Srel[((size_t)b * LQN + row0) * LQN + kp];
                float2 s1 = *(const float2*)&g_Srel[((size_t)b * LQN + row0 + 8) * LQN + kp];
                accS[3][mt][nt][0] += s0.x; accS[3][mt][nt][1] += s0.y;
                accS[3][mt][nt][2] += s1.x; accS[3][mt][nt][3] += s1.y;
            }
        }
    }

    // ---- scale + mask + row max ----
    const float* sm = (const float*)(smem + OFF_MASK);
    float mx[2][2];
    mx[0][0] = mx[0][1] = mx[1][0] = mx[1][1] = -1e30f;
    #pragma unroll
    for (int kb = 0; kb < 4; kb++)
        #pragma unroll
        for (int mt = 0; mt < 2; mt++)
            #pragma unroll
            for (int nt = 0; nt < 4; nt++) {
                int c = kb * 128 + warp_n + nt * 8 + cq;
                float ml0 = sm[c], ml1 = sm[c + 1];
                float* a = accS[kb][mt][nt];
                a[0] = fmaf(a[0], INV_SQRT_D, ml0);
                a[1] = fmaf(a[1], INV_SQRT_D, ml1);
                a[2] = fmaf(a[2], INV_SQRT_D, ml0);
                a[3] = fmaf(a[3], INV_SQRT_D, ml1);
                mx[mt][0] = fmaxf(mx[mt][0], fmaxf(a[0], a[1]));
                mx[mt][1] = fmaxf(mx[mt][1], fmaxf(a[2], a[3]));
            }
    #pragma unroll
    for (int mt = 0; mt < 2; mt++)
        #pragma unroll
        for (int h = 0; h < 2; h++) {
            mx[mt][h] = fmaxf(mx[mt][h], __shfl_xor_sync(0xffffffffu, mx[mt][h], 1));
            mx[mt][h] = fmaxf(mx[mt][h], __shfl_xor_sync(0xffffffffu, mx[mt][h], 2));
        }
    float* rmax = (float*)(smem + OFF_RMAX);
    if ((lane & 3) == 0)
        #pragma unroll
        for (int mt = 0; mt < 2; mt++)
            #pragma unroll
            for (int h = 0; h < 2; h++)
                rmax[(mt * 16 + h * 8 + rq) * 4 + wid] = mx[mt][h];
    __syncthreads();
    #pragma unroll
    for (int mt = 0; mt < 2; mt++)
        #pragma unroll
        for (int h = 0; h < 2; h++) {
            const float* r4 = &rmax[(mt * 16 + h * 8 + rq) * 4];
            mx[mt][h] = fmaxf(fmaxf(r4[0], r4[1]), fmaxf(r4[2], r4[3]));
        }

    // ---- exp + row sum ----
    float sum[2][2] = {{0.f, 0.f}, {0.f, 0.f}};
    #pragma unroll
    for (int kb = 0; kb < 4; kb++)
        #pragma unroll
        for (int mt = 0; mt < 2; mt++)
            #pragma unroll
            for (int nt = 0; nt < 4; nt++) {
                float* a = accS[kb][mt][nt];
                a[0] = __expf(a[0] - mx[mt][0]); a[1] = __expf(a[1] - mx[mt][0]);
                a[2] = __expf(a[2] - mx[mt][1]); a[3] = __expf(a[3] - mx[mt][1]);
                sum[mt][0] += a[0] + a[1]; sum[mt][1] += a[2] + a[3];
            }
    #pragma unroll
    for (int mt = 0; mt < 2; mt++)
        #pragma unroll
        for (int h = 0; h < 2; h++) {
            sum[mt][h] += __shfl_xor_sync(0xffffffffu, sum[mt][h], 1);
            sum[mt][h] += __shfl_xor_sync(0xffffffffu, sum[mt][h], 2);
        }
    float* rsum = (float*)(smem + OFF_RSUM);
    if ((lane & 3) == 0)
        #pragma unroll
        for (int mt = 0; mt < 2; mt++)
            #pragma unroll
            for (int h = 0; h < 2; h++)
                rsum[(mt * 16 + h * 8 + rq) * 4 + wid] = sum[mt][h];
    __syncthreads();
    float inv[2][2];
    #pragma unroll
    for (int mt = 0; mt < 2; mt++)
        #pragma unroll
        for (int h = 0; h < 2; h++) {
            const float* r4 = &rsum[(mt * 16 + h * 8 + rq) * 4];
            inv[mt][h] = 1.f / (r4[0] + r4[1] + r4[2] + r4[3]);
        }

    // ---- normalize + write attn (streaming stores) ----
    float* attnB = attn + ((size_t)b * LN + qt * 32) * LN;
    #pragma unroll
    for (int kb = 0; kb < 4; kb++)
        #pragma unroll
        for (int mt = 0; mt < 2; mt++) {
            const int r0 = mt * 16 + rq, r1 = r0 + 8;
            #pragma unroll
            for (int nt = 0; nt < 4; nt++) {
                int c = kb * 128 + warp_n + nt * 8 + cq;
                float* a = accS[kb][mt][nt];
                a[0] *= inv[mt][0]; a[1] *= inv[mt][0];
                a[2] *= inv[mt][1]; a[3] *= inv[mt][1];
                __stcs((float2*)(attnB + (size_t)r0 * LN + c), make_float2(a[0], a[1]));
                __stcs((float2*)(attnB + (size_t)r1 * LN + c), make_float2(a[2], a[3]));
            }
        }

    // ---- PV: stage s computes chunk s from buf[s&1], prefetches V s+2 ----
    float accO[2][4][4];
    #pragma unroll
    for (int mt = 0; mt < 2; mt++)
        #pragma unroll
        for (int nt = 0; nt < 4; nt++)
            #pragma unroll
            for (int j = 0; j < 4; j++) accO[mt][nt][j] = 0.f;

    #pragma unroll
    for (int s = 0; s < 4; s++) {
        // P chunk s -> fp16 smem (single rounding)
        #pragma unroll
        for (int mt = 0; mt < 2; mt++) {
            const int r0 = mt * 16 + rq, r1 = r0 + 8;
            #pragma unroll
            for (int nt = 0; nt < 4; nt++) {
                int c = warp_n + nt * 8 + cq;
                const float* a = accS[s][mt][nt];
                *(uint32_t*)(smem + OFF_PH + (uint32_t)(r0 * SSTR + c) * 2u) = pack_h2(a[0], a[1]);
                *(uint32_t*)(smem + OFF_PH + (uint32_t)(r1 * SSTR + c) * 2u) = pack_h2(a[2], a[3]);
            }
        }
        if (s < 3) { CP_WAIT1(); } else { CP_WAIT0(); }
        __syncthreads();
        mma_pv(sb, buf[s & 1], warp_n, lane, accO);
        __syncthreads();
        if (s < 2) {
            load_chunk(sb, buf[s & 1], g_Vh, bkv + (size_t)(s + 2) * 128 * DN, tid);
            CP_COMMIT();
        }
    }

    // ---- write out ----
    float* Og = out + ((size_t)b * LN + qt * 32) * DN;
    #pragma unroll
    for (int mt = 0; mt < 2; mt++) {
        const int r0 = mt * 16 + rq, r1 = r0 + 8;
        #pragma unroll
        for (int nt = 0; nt < 4; nt++) {
            int c = warp_n + nt * 8 + cq;
            __stcs((float2*)(Og + (size_t)r0 * DN + c), make_float2(accO[mt][nt][0], accO[mt][nt][1]));
            __stcs((float2*)(Og + (size_t)r1 * DN + c), make_float2(accO[mt][nt][2], accO[mt][nt][3]));
        }
    }
}

// ---------------------------------------------------------------------------
extern "C" void kernel_launch(void* const* d_in, const int* in_sizes, int n_in,
                              void* d_out, int out_size)
{
    const float* Q  = (const float*)d_in[0];
    const float* K  = (const float*)d_in[1];
    const float* V  = (const float*)d_in[2];
    const float* R  = (const float*)d_in[3];
    const float* M  = (const float*)d_in[4];

    float* out  = (float*)d_out;                       // [128,512,128]
    float* attn = out + (size_t)BHN * LN * DN;         // [128,512,512]

    static cudaStream_t s1;                            // LOW priority: rel backfills
    static cudaEvent_t evFork, evPrep, evF2;
    static bool init_done = false;
    if (!init_done) {
        cudaFuncSetAttribute(fused_attn, cudaFuncAttributeMaxDynamicSharedMemorySize, SMEM_T);
        int loPri, hiPri;
        cudaDeviceGetStreamPriorityRange(&loPri, &hiPri);
        cudaStreamCreateWithPriority(&s1, cudaStreamNonBlocking, loPri);
        cudaEventCreateWithFlags(&evFork, cudaEventDisableTiming);
        cudaEventCreateWithFlags(&evPrep, cudaEventDisableTiming);
        cudaEventCreateWithFlags(&evF2, cudaEventDisableTiming);
        init_done = true;
    }

    // fork: rel on low-priority s1 — co-resident with prep + fused₁
    cudaEventRecord(evFork, 0);
    cudaStreamWaitEvent(s1, evFork, 0);
    rel_kernel<<<BHN * LQN, 128, 0, s1>>>(Q, R);       // 8192 small CTAs, DRAM-bound

    dim3 gprep((BHN * LN * DN) / 4 / 256, 2);          // (8192, 2)
    prep_kernel<<<gprep, 256>>>(K, V);
    cudaEventRecord(evPrep, 0);

    // main: fused₁ (qt 0..13) — default (higher) priority, grabs SM slots
    dim3 g1(14, BHN);
    fused_attn<<<g1, 128, SMEM_T>>>(Q, M, attn, out, 0);

    // s1: fused₂ (qt 14,15) after {rel, prep}; overlaps with fused₁ tail
    cudaStreamWaitEvent(s1, evPrep, 0);
    dim3 g2(2, BHN);
    fused_attn<<<g2, 128, SMEM_T, s1>>>(Q, M, attn, out, 14);
    cudaEventRecord(evF2, s1);

    // join
    cudaStreamWaitEvent(0, evF2, 0);
}